// round 1
// baseline (speedup 1.0000x reference)
#include <cuda_runtime.h>

// Problem constants
#define BB 4
#define NN 2048
#define DD 1024
#define HH 8
#define HD 128
#define MTOT (BB * NN)  // 8192

// Scratch (allocation-free rule: __device__ globals)
static __device__ float g_q[BB * NN * DD];
static __device__ float g_k[BB * NN * DD];
static __device__ float g_v[BB * NN * DD];
static __device__ float g_a[BB * NN * DD];

// ---------------------------------------------------------------------------
// Tiled SGEMM: C[M,N] = A[M,K] @ B[K,N], row-major. Requires M%128==0,
// N%128==0, K%16==0 (true for all four GEMMs here).
// Block tile 128x128, K-step 16, 256 threads, 8x8 register tile per thread.
// ---------------------------------------------------------------------------
__global__ __launch_bounds__(256) void sgemm_nn(
    const float* __restrict__ A, const float* __restrict__ Bm,
    float* __restrict__ C, int M, int N, int K)
{
    __shared__ float As[16][128];   // A tile, K-major (transposed on store)
    __shared__ float Bs[16][128];   // B tile, natural

    const int tid = threadIdx.x;
    const int tx = tid & 15;
    const int ty = tid >> 4;
    const int rowBase = blockIdx.y * 128;
    const int colBase = blockIdx.x * 128;

    float acc[8][8];
#pragma unroll
    for (int i = 0; i < 8; i++)
#pragma unroll
        for (int j = 0; j < 8; j++) acc[i][j] = 0.f;

    const int aRow = tid >> 2;         // 0..63
    const int aCol = (tid & 3) * 4;    // 0,4,8,12
    const int bRow = tid >> 5;         // 0..7
    const int bCol = (tid & 31) * 4;   // 0..124

    for (int kt = 0; kt < K; kt += 16) {
#pragma unroll
        for (int it = 0; it < 2; it++) {
            int r = aRow + it * 64;
            float4 fa = *(const float4*)(A + (size_t)(rowBase + r) * K + kt + aCol);
            As[aCol + 0][r] = fa.x;
            As[aCol + 1][r] = fa.y;
            As[aCol + 2][r] = fa.z;
            As[aCol + 3][r] = fa.w;
            int r2 = bRow + it * 8;
            *(float4*)&Bs[r2][bCol] =
                *(const float4*)(Bm + (size_t)(kt + r2) * N + colBase + bCol);
        }
        __syncthreads();
#pragma unroll
        for (int kk = 0; kk < 16; kk++) {
            float ra[8], rb[8];
            *(float4*)&ra[0] = *(float4*)&As[kk][ty * 8];
            *(float4*)&ra[4] = *(float4*)&As[kk][ty * 8 + 4];
            *(float4*)&rb[0] = *(float4*)&Bs[kk][tx * 8];
            *(float4*)&rb[4] = *(float4*)&Bs[kk][tx * 8 + 4];
#pragma unroll
            for (int i = 0; i < 8; i++)
#pragma unroll
                for (int j = 0; j < 8; j++)
                    acc[i][j] += ra[i] * rb[j];
        }
        __syncthreads();
    }

#pragma unroll
    for (int i = 0; i < 8; i++) {
        float* Cp = C + (size_t)(rowBase + ty * 8 + i) * N + colBase + tx * 8;
        float4 o0 = {acc[i][0], acc[i][1], acc[i][2], acc[i][3]};
        float4 o1 = {acc[i][4], acc[i][5], acc[i][6], acc[i][7]};
        *(float4*)Cp = o0;
        *(float4*)(Cp + 4) = o1;
    }
}

// ---------------------------------------------------------------------------
// Flash-style attention, fp32. One block = 64 query rows of one (b, h).
// Layouts: Q/K/V/O are (B, N, H*HD) row-major (head h at column offset h*128).
// Dynamic smem:
//   Qs[128][64]  (d-major Q tile, loaded once)          32 KB
//   Ks[128][64]  (d-major K tile, per key-tile)         32 KB  -- overlaid by
//   Vs[64][128]  (natural V tile, per key-tile)         32 KB  -- same region
//   Ss[64][65]   (scores / probabilities)             ~16.6 KB
// Total 82176 bytes -> 2 blocks/SM.
// 256 threads. S-phase mapping: 16x16 threads, 4x4 outputs each.
// Row mapping (softmax/PV): thread t -> row r = t/4, d-chunk q4 = t%4 (32 cols).
// ---------------------------------------------------------------------------
__global__ __launch_bounds__(256) void attn_kernel(
    const float* __restrict__ Q, const float* __restrict__ K,
    const float* __restrict__ V, float* __restrict__ O)
{
    extern __shared__ float smem[];
    float (*Qs)[64]  = (float(*)[64])smem;            // [128][64]
    float (*Ks)[64]  = (float(*)[64])(smem + 8192);   // [128][64]
    float (*Vs)[128] = (float(*)[128])(smem + 8192);  // overlay of Ks
    float (*Ss)[65]  = (float(*)[65])(smem + 16384);  // [64][65]

    const int qt = blockIdx.x;       // query tile 0..31
    const int bh = blockIdx.y;       // 0..31
    const int b = bh >> 3;
    const int h = bh & 7;
    const int tid = threadIdx.x;
    const int tx = tid & 15;
    const int ty = tid >> 4;
    const int r  = tid >> 2;         // row 0..63
    const int q4 = tid & 3;          // d-chunk 0..3

    const size_t headOff = (size_t)b * NN * DD + (size_t)h * HD;
    const float* Qp = Q + headOff + (size_t)(qt * 64) * DD;
    const float* Kp = K + headOff;
    const float* Vp = V + headOff;

    const int lrw = tid >> 3;            // 0..31
    const int lc  = (tid & 7) << 2;      // 0..28 (x4 floats)

    // Load Q tile, d-major
#pragma unroll
    for (int it = 0; it < 8; it++) {
        int rw = lrw + (it & 1) * 32;          // 0..63
        int c  = lc + (it >> 1) * 32;          // 0..124
        float4 f = *(const float4*)(Qp + (size_t)rw * DD + c);
        Qs[c + 0][rw] = f.x;
        Qs[c + 1][rw] = f.y;
        Qs[c + 2][rw] = f.z;
        Qs[c + 3][rw] = f.w;
    }

    float acc[32];
#pragma unroll
    for (int i = 0; i < 32; i++) acc[i] = 0.f;
    float m_i = -1e30f;
    float l_i = 0.f;
    const float scale = 0.08838834764831845f;  // 1/sqrt(128)

    __syncthreads();

    for (int kt = 0; kt < 32; kt++) {
        const float* Kt = Kp + (size_t)(kt * 64) * DD;

        // --- load K tile, d-major (overwrites Vs of previous iter) ---
#pragma unroll
        for (int it = 0; it < 8; it++) {
            int rw = lrw + (it & 1) * 32;
            int c  = lc + (it >> 1) * 32;
            float4 f = *(const float4*)(Kt + (size_t)rw * DD + c);
            Ks[c + 0][rw] = f.x;
            Ks[c + 1][rw] = f.y;
            Ks[c + 2][rw] = f.z;
            Ks[c + 3][rw] = f.w;
        }
        __syncthreads();

        // --- S = Q K^T (each thread: 4x4 tile) ---
        float sv[16];
#pragma unroll
        for (int i = 0; i < 16; i++) sv[i] = 0.f;
#pragma unroll 8
        for (int d = 0; d < 128; d++) {
            float4 qa = *(const float4*)&Qs[d][ty * 4];
            float4 kb = *(const float4*)&Ks[d][tx * 4];
            sv[0]  += qa.x * kb.x; sv[1]  += qa.x * kb.y;
            sv[2]  += qa.x * kb.z; sv[3]  += qa.x * kb.w;
            sv[4]  += qa.y * kb.x; sv[5]  += qa.y * kb.y;
            sv[6]  += qa.y * kb.z; sv[7]  += qa.y * kb.w;
            sv[8]  += qa.z * kb.x; sv[9]  += qa.z * kb.y;
            sv[10] += qa.z * kb.z; sv[11] += qa.z * kb.w;
            sv[12] += qa.w * kb.x; sv[13] += qa.w * kb.y;
            sv[14] += qa.w * kb.z; sv[15] += qa.w * kb.w;
        }
#pragma unroll
        for (int i = 0; i < 4; i++)
#pragma unroll
            for (int j = 0; j < 4; j++)
                Ss[ty * 4 + i][tx * 4 + j] = sv[i * 4 + j] * scale;
        __syncthreads();

        // --- load V tile (overwrites Ks; all S reads are done) ---
#pragma unroll
        for (int it = 0; it < 8; it++) {
            int f4i = tid + 256 * it;
            int rw = f4i >> 5;              // 0..63
            int c4 = (f4i & 31) << 2;       // 0..124
            *(float4*)&Vs[rw][c4] =
                *(const float4*)(Vp + (size_t)(kt * 64 + rw) * DD + c4);
        }

        // --- online softmax (row mapping: 4 threads per row) ---
        float tmax = -1e30f;
#pragma unroll
        for (int kx = 0; kx < 16; kx++)
            tmax = fmaxf(tmax, Ss[r][q4 * 16 + kx]);
        tmax = fmaxf(tmax, __shfl_xor_sync(0xffffffffu, tmax, 1));
        tmax = fmaxf(tmax, __shfl_xor_sync(0xffffffffu, tmax, 2));
        float m_new = fmaxf(m_i, tmax);
        float alpha = __expf(m_i - m_new);
        l_i *= alpha;
#pragma unroll
        for (int i = 0; i < 32; i++) acc[i] *= alpha;
        float lsum = 0.f;
#pragma unroll
        for (int kx = 0; kx < 16; kx++) {
            float p = __expf(Ss[r][q4 * 16 + kx] - m_new);
            Ss[r][q4 * 16 + kx] = p;
            lsum += p;
        }
        lsum += __shfl_xor_sync(0xffffffffu, lsum, 1);
        lsum += __shfl_xor_sync(0xffffffffu, lsum, 2);
        l_i += lsum;
        m_i = m_new;
        __syncthreads();   // Vs loaded AND Ss probabilities written

        // --- O += P V  (thread owns row r, cols q4*32..q4*32+31) ---
#pragma unroll 4
        for (int kj = 0; kj < 64; kj++) {
            float p = Ss[r][kj];
#pragma unroll
            for (int ii = 0; ii < 8; ii++) {
                float4 v = *(const float4*)&Vs[kj][q4 * 32 + ii * 4];
                acc[ii * 4 + 0] += p * v.x;
                acc[ii * 4 + 1] += p * v.y;
                acc[ii * 4 + 2] += p * v.z;
                acc[ii * 4 + 3] += p * v.w;
            }
        }
        __syncthreads();   // done with Vs & Ss before next iter overwrites
    }

    // --- epilogue ---
    float inv = 1.f / l_i;
    float* Op = O + headOff + (size_t)(qt * 64 + r) * DD + q4 * 32;
#pragma unroll
    for (int ii = 0; ii < 8; ii++) {
        float4 o;
        o.x = acc[ii * 4 + 0] * inv;
        o.y = acc[ii * 4 + 1] * inv;
        o.z = acc[ii * 4 + 2] * inv;
        o.w = acc[ii * 4 + 3] * inv;
        *(float4*)(Op + ii * 4) = o;
    }
}

// ---------------------------------------------------------------------------
extern "C" void kernel_launch(void* const* d_in, const int* in_sizes, int n_in,
                              void* d_out, int out_size)
{
    const float* x  = (const float*)d_in[0];
    const float* Wq = (const float*)d_in[1];
    const float* Wk = (const float*)d_in[2];
    const float* Wv = (const float*)d_in[3];
    const float* Wo = (const float*)d_in[4];
    float* out = (float*)d_out;

    float *q, *k, *v, *a;
    cudaGetSymbolAddress((void**)&q, g_q);
    cudaGetSymbolAddress((void**)&k, g_k);
    cudaGetSymbolAddress((void**)&v, g_v);
    cudaGetSymbolAddress((void**)&a, g_a);

    const int attn_smem = (16384 + 64 * 65) * 4;  // 82176 bytes
    cudaFuncSetAttribute(attn_kernel,
                         cudaFuncAttributeMaxDynamicSharedMemorySize, attn_smem);

    dim3 gproj(DD / 128, MTOT / 128);  // (8, 64)
    sgemm_nn<<<gproj, 256>>>(x, Wq, q, MTOT, DD, DD);
    sgemm_nn<<<gproj, 256>>>(x, Wk, k, MTOT, DD, DD);
    sgemm_nn<<<gproj, 256>>>(x, Wv, v, MTOT, DD, DD);

    attn_kernel<<<dim3(NN / 64, BB * HH), 256, attn_smem>>>(q, k, v, a);

    sgemm_nn<<<gproj, 256>>>(a, Wo, out, MTOT, DD, DD);
}

// round 2
// speedup vs baseline: 7.8385x; 7.8385x over previous
#include <cuda_runtime.h>
#include <cstdint>

#define BB 4
#define NN 2048
#define DD 1024
#define HH 8
#define MTOT (BB * NN)  // 8192

// Scratch (allocation-free rule: __device__ globals)
static __device__ float g_q[BB * NN * DD];
static __device__ float g_k[BB * NN * DD];
static __device__ float g_v[BB * NN * DD];
static __device__ float g_a[BB * NN * DD];

// ---------------------------------------------------------------------------
// tf32 helpers
// ---------------------------------------------------------------------------
__device__ __forceinline__ uint32_t f2tf(float f) {
    uint32_t u;
    asm("cvt.rna.tf32.f32 %0, %1;" : "=r"(u) : "f"(f));
    return u;
}

__device__ __forceinline__ void mma_tf32(float d[4], const uint32_t a[4],
                                         const uint32_t b[2]) {
    asm volatile(
        "mma.sync.aligned.m16n8k8.row.col.f32.tf32.tf32.f32 "
        "{%0,%1,%2,%3}, {%4,%5,%6,%7}, {%8,%9}, {%0,%1,%2,%3};"
        : "+f"(d[0]), "+f"(d[1]), "+f"(d[2]), "+f"(d[3])
        : "r"(a[0]), "r"(a[1]), "r"(a[2]), "r"(a[3]), "r"(b[0]), "r"(b[1]));
}

// ---------------------------------------------------------------------------
// tf32 tensor-core GEMM: C[M,N] = A[M,K] @ B[K,N], row-major fp32 in/out.
// Block tile 128x128, BK=32, 256 threads (8 warps as 2m x 4n), warp tile 64x32.
// Smem strides 36 / 132 words (== 4 mod 32) -> conflict-free fragment LDS.
// ---------------------------------------------------------------------------
#define GA_STRIDE 36
#define GB_STRIDE 132

__global__ __launch_bounds__(256, 2) void gemm_tf32(
    const float* __restrict__ A, const float* __restrict__ Bm,
    float* __restrict__ C, int M, int N, int K)
{
    __shared__ uint32_t As[128 * GA_STRIDE];
    __shared__ uint32_t Bs[32 * GB_STRIDE];

    const int tid = threadIdx.x;
    const int lane = tid & 31;
    const int wid = tid >> 5;
    const int wm = (wid & 1) * 64;   // warp row offset
    const int wn = (wid >> 1) * 32;  // warp col offset
    const int g  = lane >> 2;        // group id 0..7
    const int c4 = lane & 3;         // thread-in-group 0..3
    const int rowBase = blockIdx.y * 128;
    const int colBase = blockIdx.x * 128;

    float acc[4][4][4] = {};

    const int arow = tid >> 2;        // 0..63 (two halves of 128)
    const int ak   = (tid & 3) * 8;   // k offset 0,8,16,24
    const int brow = tid >> 3;        // 0..31
    const int bc   = (tid & 7) * 4;   // col offset (x4 strides of 32)

    for (int kt = 0; kt < K; kt += 32) {
        __syncthreads();  // prior compute done before overwrite
        // A tile 128x32 (row-major, k-contiguous)
#pragma unroll
        for (int hh = 0; hh < 2; hh++) {
            int r = arow + hh * 64;
            const float* ap = A + (size_t)(rowBase + r) * K + kt + ak;
            float4 f0 = *(const float4*)(ap);
            float4 f1 = *(const float4*)(ap + 4);
            uint4 u0 = {f2tf(f0.x), f2tf(f0.y), f2tf(f0.z), f2tf(f0.w)};
            uint4 u1 = {f2tf(f1.x), f2tf(f1.y), f2tf(f1.z), f2tf(f1.w)};
            *(uint4*)&As[r * GA_STRIDE + ak] = u0;
            *(uint4*)&As[r * GA_STRIDE + ak + 4] = u1;
        }
        // B tile 32x128 (natural [k][n])
#pragma unroll
        for (int hh = 0; hh < 4; hh++) {
            int c = bc + hh * 32;
            float4 f = *(const float4*)(Bm + (size_t)(kt + brow) * N + colBase + c);
            uint4 u = {f2tf(f.x), f2tf(f.y), f2tf(f.z), f2tf(f.w)};
            *(uint4*)&Bs[brow * GB_STRIDE + c] = u;
        }
        __syncthreads();

#pragma unroll
        for (int ks = 0; ks < 4; ks++) {
            uint32_t a[4][4], b[4][2];
#pragma unroll
            for (int mt = 0; mt < 4; mt++) {
                int r = wm + mt * 16 + g;
                a[mt][0] = As[r * GA_STRIDE + ks * 8 + c4];
                a[mt][1] = As[(r + 8) * GA_STRIDE + ks * 8 + c4];
                a[mt][2] = As[r * GA_STRIDE + ks * 8 + 4 + c4];
                a[mt][3] = As[(r + 8) * GA_STRIDE + ks * 8 + 4 + c4];
            }
#pragma unroll
            for (int nt = 0; nt < 4; nt++) {
                int n = wn + nt * 8 + g;
                b[nt][0] = Bs[(ks * 8 + c4) * GB_STRIDE + n];
                b[nt][1] = Bs[(ks * 8 + 4 + c4) * GB_STRIDE + n];
            }
#pragma unroll
            for (int mt = 0; mt < 4; mt++)
#pragma unroll
                for (int nt = 0; nt < 4; nt++)
                    mma_tf32(acc[mt][nt], a[mt], b[nt]);
        }
    }

    // epilogue: C fragment layout (g = row, 2*c4 = col pair)
#pragma unroll
    for (int mt = 0; mt < 4; mt++) {
        int r0 = rowBase + wm + mt * 16 + g;
#pragma unroll
        for (int nt = 0; nt < 4; nt++) {
            int cc = colBase + wn + nt * 8 + 2 * c4;
            *(float2*)(C + (size_t)r0 * N + cc) =
                make_float2(acc[mt][nt][0], acc[mt][nt][1]);
            *(float2*)(C + (size_t)(r0 + 8) * N + cc) =
                make_float2(acc[mt][nt][2], acc[mt][nt][3]);
        }
    }
}

// ---------------------------------------------------------------------------
// Flash attention with tf32 tensor cores.
// Block = 128 query rows of one (b,h). 8 warps, warp owns 16 rows (full width).
// KV tiles of 64. P routed through smem (warp-private rows -> no block sync).
// smem: Qs[128][132] + Ks[64][132] + Vs[64][132] + Ps[128][68] (uint32 tf32)
//     = 169,984 bytes dynamic.
// ---------------------------------------------------------------------------
#define QS_STRIDE 132
#define KS_STRIDE 132
#define PS_STRIDE 68

__global__ __launch_bounds__(256, 1) void attn_tf32(
    const float* __restrict__ Q, const float* __restrict__ K,
    const float* __restrict__ V, float* __restrict__ O)
{
    extern __shared__ uint32_t sm[];
    uint32_t* Qs = sm;                    // 128*132
    uint32_t* Ks = Qs + 128 * QS_STRIDE;  // 64*132
    uint32_t* Vs = Ks + 64 * KS_STRIDE;   // 64*132
    uint32_t* Ps = Vs + 64 * KS_STRIDE;   // 128*68

    const int tid = threadIdx.x;
    const int lane = tid & 31;
    const int wid = tid >> 5;
    const int g  = lane >> 2;
    const int c4 = lane & 3;
    const int qt = blockIdx.x;   // 0..15
    const int bh = blockIdx.y;   // 0..31
    const int b = bh >> 3;
    const int h = bh & 7;

    const size_t headOff = (size_t)b * NN * DD + (size_t)h * 128;
    const float* Qp = Q + headOff + (size_t)(qt * 128) * DD;
    const float* Kp = K + headOff;
    const float* Vp = V + headOff;
    const float scale = 0.08838834764831845f;  // 1/sqrt(128)

    // Load Q tile (scaled, tf32)
#pragma unroll
    for (int i = 0; i < 16; i++) {
        int idx = tid + 256 * i;
        int r = idx >> 5, c = (idx & 31) * 4;
        float4 f = *(const float4*)(Qp + (size_t)r * DD + c);
        uint4 u = {f2tf(f.x * scale), f2tf(f.y * scale),
                   f2tf(f.z * scale), f2tf(f.w * scale)};
        *(uint4*)&Qs[r * QS_STRIDE + c] = u;
    }

    float o[16][4] = {};
    float m_lo = -1e30f, m_hi = -1e30f, l_lo = 0.f, l_hi = 0.f;
    const int q0 = wid * 16 + g;  // this thread's low row

    for (int kt = 0; kt < 32; kt++) {
        __syncthreads();  // prior PV reads of Vs done; also covers Q on iter 0
        const float* Kt = Kp + (size_t)(kt * 64) * DD;
        const float* Vt = Vp + (size_t)(kt * 64) * DD;
#pragma unroll
        for (int i = 0; i < 8; i++) {
            int idx = tid + 256 * i;
            int r = idx >> 5, c = (idx & 31) * 4;
            float4 fk = *(const float4*)(Kt + (size_t)r * DD + c);
            uint4 uk = {f2tf(fk.x), f2tf(fk.y), f2tf(fk.z), f2tf(fk.w)};
            *(uint4*)&Ks[r * KS_STRIDE + c] = uk;
            float4 fv = *(const float4*)(Vt + (size_t)r * DD + c);
            uint4 uv = {f2tf(fv.x), f2tf(fv.y), f2tf(fv.z), f2tf(fv.w)};
            *(uint4*)&Vs[r * KS_STRIDE + c] = uv;
        }
        __syncthreads();

        // --- S = Q K^T (warp rows q0-block, 64 kv cols) ---
        float s[8][4] = {};
#pragma unroll
        for (int ks = 0; ks < 16; ks++) {
            uint32_t a[4];
            a[0] = Qs[q0 * QS_STRIDE + ks * 8 + c4];
            a[1] = Qs[(q0 + 8) * QS_STRIDE + ks * 8 + c4];
            a[2] = Qs[q0 * QS_STRIDE + ks * 8 + 4 + c4];
            a[3] = Qs[(q0 + 8) * QS_STRIDE + ks * 8 + 4 + c4];
#pragma unroll
            for (int nt = 0; nt < 8; nt++) {
                uint32_t bf[2];
                bf[0] = Ks[(nt * 8 + g) * KS_STRIDE + ks * 8 + c4];
                bf[1] = Ks[(nt * 8 + g) * KS_STRIDE + ks * 8 + 4 + c4];
                mma_tf32(s[nt], a, bf);
            }
        }

        // --- online softmax (rows q0 and q0+8; 4 lanes per row) ---
        float mx_lo = -1e30f, mx_hi = -1e30f;
#pragma unroll
        for (int nt = 0; nt < 8; nt++) {
            mx_lo = fmaxf(mx_lo, fmaxf(s[nt][0], s[nt][1]));
            mx_hi = fmaxf(mx_hi, fmaxf(s[nt][2], s[nt][3]));
        }
        mx_lo = fmaxf(mx_lo, __shfl_xor_sync(0xffffffffu, mx_lo, 1));
        mx_lo = fmaxf(mx_lo, __shfl_xor_sync(0xffffffffu, mx_lo, 2));
        mx_hi = fmaxf(mx_hi, __shfl_xor_sync(0xffffffffu, mx_hi, 1));
        mx_hi = fmaxf(mx_hi, __shfl_xor_sync(0xffffffffu, mx_hi, 2));
        float mnew_lo = fmaxf(m_lo, mx_lo);
        float mnew_hi = fmaxf(m_hi, mx_hi);
        float al_lo = __expf(m_lo - mnew_lo);
        float al_hi = __expf(m_hi - mnew_hi);
        float sum_lo = 0.f, sum_hi = 0.f;
#pragma unroll
        for (int nt = 0; nt < 8; nt++) {
            float p0 = __expf(s[nt][0] - mnew_lo);
            float p1 = __expf(s[nt][1] - mnew_lo);
            float p2 = __expf(s[nt][2] - mnew_hi);
            float p3 = __expf(s[nt][3] - mnew_hi);
            sum_lo += p0 + p1;
            sum_hi += p2 + p3;
            uint2 ulo = {f2tf(p0), f2tf(p1)};
            uint2 uhi = {f2tf(p2), f2tf(p3)};
            *(uint2*)&Ps[q0 * PS_STRIDE + nt * 8 + 2 * c4] = ulo;
            *(uint2*)&Ps[(q0 + 8) * PS_STRIDE + nt * 8 + 2 * c4] = uhi;
        }
        sum_lo += __shfl_xor_sync(0xffffffffu, sum_lo, 1);
        sum_lo += __shfl_xor_sync(0xffffffffu, sum_lo, 2);
        sum_hi += __shfl_xor_sync(0xffffffffu, sum_hi, 1);
        sum_hi += __shfl_xor_sync(0xffffffffu, sum_hi, 2);
        l_lo = l_lo * al_lo + sum_lo;
        l_hi = l_hi * al_hi + sum_hi;
        m_lo = mnew_lo;
        m_hi = mnew_hi;
#pragma unroll
        for (int nt = 0; nt < 16; nt++) {
            o[nt][0] *= al_lo;
            o[nt][1] *= al_lo;
            o[nt][2] *= al_hi;
            o[nt][3] *= al_hi;
        }
        __syncwarp();  // Ps rows are warp-private; warp-level visibility only

        // --- O += P V ---
#pragma unroll
        for (int ks = 0; ks < 8; ks++) {
            uint32_t a[4];
            a[0] = Ps[q0 * PS_STRIDE + ks * 8 + c4];
            a[1] = Ps[(q0 + 8) * PS_STRIDE + ks * 8 + c4];
            a[2] = Ps[q0 * PS_STRIDE + ks * 8 + 4 + c4];
            a[3] = Ps[(q0 + 8) * PS_STRIDE + ks * 8 + 4 + c4];
#pragma unroll
            for (int nt = 0; nt < 16; nt++) {
                uint32_t bf[2];
                bf[0] = Vs[(ks * 8 + c4) * KS_STRIDE + nt * 8 + g];
                bf[1] = Vs[(ks * 8 + 4 + c4) * KS_STRIDE + nt * 8 + g];
                mma_tf32(o[nt], a, bf);
            }
        }
    }

    // --- epilogue ---
    float inv_lo = 1.f / l_lo;
    float inv_hi = 1.f / l_hi;
    float* Op = O + headOff + (size_t)(qt * 128) * DD;
#pragma unroll
    for (int nt = 0; nt < 16; nt++) {
        int cc = nt * 8 + 2 * c4;
        *(float2*)(Op + (size_t)q0 * DD + cc) =
            make_float2(o[nt][0] * inv_lo, o[nt][1] * inv_lo);
        *(float2*)(Op + (size_t)(q0 + 8) * DD + cc) =
            make_float2(o[nt][2] * inv_hi, o[nt][3] * inv_hi);
    }
}

// ---------------------------------------------------------------------------
extern "C" void kernel_launch(void* const* d_in, const int* in_sizes, int n_in,
                              void* d_out, int out_size)
{
    const float* x  = (const float*)d_in[0];
    const float* Wq = (const float*)d_in[1];
    const float* Wk = (const float*)d_in[2];
    const float* Wv = (const float*)d_in[3];
    const float* Wo = (const float*)d_in[4];
    float* out = (float*)d_out;

    float *q, *k, *v, *a;
    cudaGetSymbolAddress((void**)&q, g_q);
    cudaGetSymbolAddress((void**)&k, g_k);
    cudaGetSymbolAddress((void**)&v, g_v);
    cudaGetSymbolAddress((void**)&a, g_a);

    const int attn_smem =
        (128 * QS_STRIDE + 64 * KS_STRIDE + 64 * KS_STRIDE + 128 * PS_STRIDE) * 4;
    cudaFuncSetAttribute(attn_tf32,
                         cudaFuncAttributeMaxDynamicSharedMemorySize, attn_smem);

    dim3 gproj(DD / 128, MTOT / 128);  // (8, 64)
    gemm_tf32<<<gproj, 256>>>(x, Wq, q, MTOT, DD, DD);
    gemm_tf32<<<gproj, 256>>>(x, Wk, k, MTOT, DD, DD);
    gemm_tf32<<<gproj, 256>>>(x, Wv, v, MTOT, DD, DD);

    attn_tf32<<<dim3(NN / 128, BB * HH), 256, attn_smem>>>(q, k, v, a);

    gemm_tf32<<<gproj, 256>>>(a, Wo, out, MTOT, DD, DD);
}

// round 4
// speedup vs baseline: 7.8851x; 1.0059x over previous
#include <cuda_runtime.h>
#include <cstdint>

#define BB 4
#define NN 2048
#define DD 1024
#define HH 8
#define MTOT (BB * NN)  // 8192

static __device__ float g_q[BB * NN * DD];
static __device__ float g_k[BB * NN * DD];
static __device__ float g_v[BB * NN * DD];
static __device__ float g_a[BB * NN * DD];

// ---------------------------------------------------------------------------
__device__ __forceinline__ uint32_t f2tf(float f) {
    uint32_t u;
    asm("cvt.rna.tf32.f32 %0, %1;" : "=r"(u) : "f"(f));
    return u;
}

__device__ __forceinline__ void mma_tf32(float d[4], const uint32_t a[4],
                                         const uint32_t b[2]) {
    asm volatile(
        "mma.sync.aligned.m16n8k8.row.col.f32.tf32.tf32.f32 "
        "{%0,%1,%2,%3}, {%4,%5,%6,%7}, {%8,%9}, {%0,%1,%2,%3};"
        : "+f"(d[0]), "+f"(d[1]), "+f"(d[2]), "+f"(d[3])
        : "r"(a[0]), "r"(a[1]), "r"(a[2]), "r"(a[3]), "r"(b[0]), "r"(b[1]));
}

__device__ __forceinline__ void cp16(void* smem, const void* g) {
    uint32_t s = (uint32_t)__cvta_generic_to_shared(smem);
    asm volatile("cp.async.ca.shared.global [%0], [%1], 16;" :: "r"(s), "l"(g));
}

// ---------------------------------------------------------------------------
// tf32 GEMM, cp.async 2-stage pipeline. Block tile 128x128, BK=32, 256 thr.
// gridDim.z selects (W,C) pair -> fused QKV projection in one launch.
// Dynamic smem: 2*(128*36 + 32*136)*4 = 71680 B -> 2 blocks/SM.
// ---------------------------------------------------------------------------
#define GA 36
#define GB 136

__global__ __launch_bounds__(256, 2) void gemm_tf32(
    const float* __restrict__ A,
    const float* __restrict__ W0, const float* __restrict__ W1,
    const float* __restrict__ W2,
    float* __restrict__ C0, float* __restrict__ C1, float* __restrict__ C2,
    int M, int N, int K)
{
    const float* Bm = (blockIdx.z == 0) ? W0 : (blockIdx.z == 1) ? W1 : W2;
    float* C = (blockIdx.z == 0) ? C0 : (blockIdx.z == 1) ? C1 : C2;

    extern __shared__ float gsm[];
    float* As = gsm;                 // [2][128*GA]
    float* Bs = gsm + 2 * 128 * GA;  // [2][32*GB]

    const int tid = threadIdx.x;
    const int lane = tid & 31;
    const int wid = tid >> 5;
    const int wm = (wid & 1) * 64;
    const int wn = (wid >> 1) * 32;
    const int g  = lane >> 2;
    const int c4 = lane & 3;
    const int rowBase = blockIdx.y * 128;
    const int colBase = blockIdx.x * 128;

    float acc[4][4][4] = {};

    const int arow = tid >> 2;
    const int ak   = (tid & 3) * 8;
    const int brow = tid >> 3;
    const int bc   = (tid & 7) * 4;

    auto load_stage = [&](int kt, int bufi) {
        float* Asb = As + bufi * 128 * GA;
        float* Bsb = Bs + bufi * 32 * GB;
#pragma unroll
        for (int hh = 0; hh < 2; hh++) {
            int r = arow + hh * 64;
            const float* ap = A + (size_t)(rowBase + r) * K + kt + ak;
            cp16(&Asb[r * GA + ak], ap);
            cp16(&Asb[r * GA + ak + 4], ap + 4);
        }
#pragma unroll
        for (int hh = 0; hh < 4; hh++) {
            int c = bc + hh * 32;
            cp16(&Bsb[brow * GB + c],
                 Bm + (size_t)(kt + brow) * N + colBase + c);
        }
    };

    load_stage(0, 0);
    asm volatile("cp.async.commit_group;" ::: "memory");

    const int T = K / 32;
    for (int t = 0; t < T; t++) {
        if (t + 1 < T) {
            load_stage((t + 1) * 32, (t + 1) & 1);
            asm volatile("cp.async.commit_group;" ::: "memory");
            asm volatile("cp.async.wait_group 1;" ::: "memory");
        } else {
            asm volatile("cp.async.wait_group 0;" ::: "memory");
        }
        __syncthreads();

        const float* Asb = As + (t & 1) * 128 * GA;
        const float* Bsb = Bs + (t & 1) * 32 * GB;
#pragma unroll
        for (int ks = 0; ks < 4; ks++) {
            uint32_t a[4][4], b[4][2];
#pragma unroll
            for (int mt = 0; mt < 4; mt++) {
                int r = wm + mt * 16 + g;
                a[mt][0] = f2tf(Asb[r * GA + ks * 8 + c4]);
                a[mt][1] = f2tf(Asb[(r + 8) * GA + ks * 8 + c4]);
                a[mt][2] = f2tf(Asb[r * GA + ks * 8 + 4 + c4]);
                a[mt][3] = f2tf(Asb[(r + 8) * GA + ks * 8 + 4 + c4]);
            }
#pragma unroll
            for (int nt = 0; nt < 4; nt++) {
                int n = wn + nt * 8 + g;
                b[nt][0] = f2tf(Bsb[(ks * 8 + c4) * GB + n]);
                b[nt][1] = f2tf(Bsb[(ks * 8 + 4 + c4) * GB + n]);
            }
#pragma unroll
            for (int mt = 0; mt < 4; mt++)
#pragma unroll
                for (int nt = 0; nt < 4; nt++)
                    mma_tf32(acc[mt][nt], a[mt], b[nt]);
        }
        __syncthreads();
    }

#pragma unroll
    for (int mt = 0; mt < 4; mt++) {
        int r0 = rowBase + wm + mt * 16 + g;
#pragma unroll
        for (int nt = 0; nt < 4; nt++) {
            int cc = colBase + wn + nt * 8 + 2 * c4;
            *(float2*)(C + (size_t)r0 * N + cc) =
                make_float2(acc[mt][nt][0], acc[mt][nt][1]);
            *(float2*)(C + (size_t)(r0 + 8) * N + cc) =
                make_float2(acc[mt][nt][2], acc[mt][nt][3]);
        }
    }
}

// ---------------------------------------------------------------------------
// Flash attention, tf32 MMA, 512 threads (16 warps).
// Block = 128 query rows of one (b,h). KV tile 64.
// Warp (r2 = wid&7, c2 = wid>>3):
//   S-phase  -> rows [16r2,16r2+16) x kv cols [32c2, 32c2+32)
//   PV-phase -> rows [16r2,16r2+16) x d  cols [64c2, 64c2+64)   (8 n-tiles!)
// Row max/sum combined across the 2 c2-warps via Mred/Lred smem.
// ---------------------------------------------------------------------------
#define QS_S 132
#define KS_S 136
#define PS_S 68

__global__ __launch_bounds__(512, 1) void attn_tf32(
    const float* __restrict__ Q, const float* __restrict__ K,
    const float* __restrict__ V, float* __restrict__ O)
{
    extern __shared__ uint32_t sm[];
    uint32_t* Qs = sm;                      // 128*132
    uint32_t* Ks = Qs + 128 * QS_S;         // 64*136
    uint32_t* Vs = Ks + 64 * KS_S;          // 64*136
    uint32_t* Ps = Vs + 64 * KS_S;          // 128*68
    float* Mred = (float*)(Ps + 128 * PS_S);  // [2][128]
    float* Lred = Mred + 256;                 // [2][128]

    const int tid = threadIdx.x;
    const int lane = tid & 31;
    const int wid = tid >> 5;
    const int r2 = wid & 7;
    const int c2 = wid >> 3;
    const int g  = lane >> 2;
    const int c4 = lane & 3;
    const int qt = blockIdx.x;
    const int bh = blockIdx.y;
    const int b = bh >> 3;
    const int h = bh & 7;

    const int q0 = r2 * 16 + g;
    const int q1 = q0 + 8;

    const size_t headOff = (size_t)b * NN * DD + (size_t)h * 128;
    const float* Qp = Q + headOff + (size_t)(qt * 128) * DD;
    const float* Kp = K + headOff;
    const float* Vp = V + headOff;
    const float scale = 0.08838834764831845f;  // 1/sqrt(128)

    // Q tile (scaled, tf32): 4096 float4 / 512 thr = 8 each
#pragma unroll
    for (int i = 0; i < 8; i++) {
        int idx = tid + 512 * i;
        int r = idx >> 5, c = (idx & 31) * 4;
        float4 f = *(const float4*)(Qp + (size_t)r * DD + c);
        uint4 u = {f2tf(f.x * scale), f2tf(f.y * scale),
                   f2tf(f.z * scale), f2tf(f.w * scale)};
        *(uint4*)&Qs[r * QS_S + c] = u;
    }

    float o[8][4] = {};   // 16 rows x 64 d-cols per warp
    float m_lo = -1e30f, m_hi = -1e30f, l_lo = 0.f, l_hi = 0.f;

    for (int kt = 0; kt < 32; kt++) {
        __syncthreads();  // prior-iter Vs/Ps reads done (covers Q on iter 0)
        const float* Kt = Kp + (size_t)(kt * 64) * DD;
        const float* Vt = Vp + (size_t)(kt * 64) * DD;
#pragma unroll
        for (int i = 0; i < 4; i++) {
            int idx = tid + 512 * i;
            int r = idx >> 5, c = (idx & 31) * 4;
            float4 fk = *(const float4*)(Kt + (size_t)r * DD + c);
            uint4 uk = {f2tf(fk.x), f2tf(fk.y), f2tf(fk.z), f2tf(fk.w)};
            *(uint4*)&Ks[r * KS_S + c] = uk;
            float4 fv = *(const float4*)(Vt + (size_t)r * DD + c);
            uint4 uv = {f2tf(fv.x), f2tf(fv.y), f2tf(fv.z), f2tf(fv.w)};
            *(uint4*)&Vs[r * KS_S + c] = uv;
        }
        __syncthreads();

        // --- S = Q K^T : warp tile 16 x 32 ---
        float s[4][4] = {};
#pragma unroll
        for (int ks = 0; ks < 16; ks++) {
            uint32_t a[4];
            a[0] = Qs[q0 * QS_S + ks * 8 + c4];
            a[1] = Qs[q1 * QS_S + ks * 8 + c4];
            a[2] = Qs[q0 * QS_S + ks * 8 + 4 + c4];
            a[3] = Qs[q1 * QS_S + ks * 8 + 4 + c4];
#pragma unroll
            for (int nt = 0; nt < 4; nt++) {
                uint32_t bf[2];
                int n = c2 * 32 + nt * 8 + g;
                bf[0] = Ks[n * KS_S + ks * 8 + c4];
                bf[1] = Ks[n * KS_S + ks * 8 + 4 + c4];
                mma_tf32(s[nt], a, bf);
            }
        }

        // --- warp-local row max over 32 kv cols ---
        float pm_lo = -1e30f, pm_hi = -1e30f;
#pragma unroll
        for (int nt = 0; nt < 4; nt++) {
            pm_lo = fmaxf(pm_lo, fmaxf(s[nt][0], s[nt][1]));
            pm_hi = fmaxf(pm_hi, fmaxf(s[nt][2], s[nt][3]));
        }
        pm_lo = fmaxf(pm_lo, __shfl_xor_sync(0xffffffffu, pm_lo, 1));
        pm_lo = fmaxf(pm_lo, __shfl_xor_sync(0xffffffffu, pm_lo, 2));
        pm_hi = fmaxf(pm_hi, __shfl_xor_sync(0xffffffffu, pm_hi, 1));
        pm_hi = fmaxf(pm_hi, __shfl_xor_sync(0xffffffffu, pm_hi, 2));
        if (c4 == 0) {
            Mred[c2 * 128 + q0] = pm_lo;
            Mred[c2 * 128 + q1] = pm_hi;
        }
        __syncthreads();

        float mnew_lo = fmaxf(m_lo, fmaxf(Mred[q0], Mred[128 + q0]));
        float mnew_hi = fmaxf(m_hi, fmaxf(Mred[q1], Mred[128 + q1]));
        float al_lo = __expf(m_lo - mnew_lo);
        float al_hi = __expf(m_hi - mnew_hi);
        m_lo = mnew_lo;
        m_hi = mnew_hi;

        float sum_lo = 0.f, sum_hi = 0.f;
#pragma unroll
        for (int nt = 0; nt < 4; nt++) {
            float p0 = __expf(s[nt][0] - mnew_lo);
            float p1 = __expf(s[nt][1] - mnew_lo);
            float p2 = __expf(s[nt][2] - mnew_hi);
            float p3 = __expf(s[nt][3] - mnew_hi);
            sum_lo += p0 + p1;
            sum_hi += p2 + p3;
            int cc = c2 * 32 + nt * 8 + 2 * c4;
            uint2 ulo = {f2tf(p0), f2tf(p1)};
            uint2 uhi = {f2tf(p2), f2tf(p3)};
            *(uint2*)&Ps[q0 * PS_S + cc] = ulo;
            *(uint2*)&Ps[q1 * PS_S + cc] = uhi;
        }
        sum_lo += __shfl_xor_sync(0xffffffffu, sum_lo, 1);
        sum_lo += __shfl_xor_sync(0xffffffffu, sum_lo, 2);
        sum_hi += __shfl_xor_sync(0xffffffffu, sum_hi, 1);
        sum_hi += __shfl_xor_sync(0xffffffffu, sum_hi, 2);
        if (c4 == 0) {
            Lred[c2 * 128 + q0] = sum_lo;
            Lred[c2 * 128 + q1] = sum_hi;
        }

        // rescale O while sums land
#pragma unroll
        for (int nt = 0; nt < 8; nt++) {
            o[nt][0] *= al_lo;
            o[nt][1] *= al_lo;
            o[nt][2] *= al_hi;
            o[nt][3] *= al_hi;
        }
        __syncthreads();  // Ps + Lred visible

        l_lo = l_lo * al_lo + Lred[q0] + Lred[128 + q0];
        l_hi = l_hi * al_hi + Lred[q1] + Lred[128 + q1];

        // --- O += P V : warp tile 16 rows x 64 d-cols, k = 64 ---
#pragma unroll
        for (int ks = 0; ks < 8; ks++) {
            uint32_t a[4];
            a[0] = Ps[q0 * PS_S + ks * 8 + c4];
            a[1] = Ps[q1 * PS_S + ks * 8 + c4];
            a[2] = Ps[q0 * PS_S + ks * 8 + 4 + c4];
            a[3] = Ps[q1 * PS_S + ks * 8 + 4 + c4];
#pragma unroll
            for (int nt = 0; nt < 8; nt++) {
                uint32_t bf[2];
                int n = c2 * 64 + nt * 8 + g;
                bf[0] = Vs[(ks * 8 + c4) * KS_S + n];
                bf[1] = Vs[(ks * 8 + 4 + c4) * KS_S + n];
                mma_tf32(o[nt], a, bf);
            }
        }
    }

    // --- epilogue ---
    float inv_lo = 1.f / l_lo;
    float inv_hi = 1.f / l_hi;
    float* Op = O + headOff + (size_t)(qt * 128) * DD;
#pragma unroll
    for (int nt = 0; nt < 8; nt++) {
        int cc = c2 * 64 + nt * 8 + 2 * c4;
        *(float2*)(Op + (size_t)q0 * DD + cc) =
            make_float2(o[nt][0] * inv_lo, o[nt][1] * inv_lo);
        *(float2*)(Op + (size_t)q1 * DD + cc) =
            make_float2(o[nt][2] * inv_hi, o[nt][3] * inv_hi);
    }
}

// ---------------------------------------------------------------------------
extern "C" void kernel_launch(void* const* d_in, const int* in_sizes, int n_in,
                              void* d_out, int out_size)
{
    const float* x  = (const float*)d_in[0];
    const float* Wq = (const float*)d_in[1];
    const float* Wk = (const float*)d_in[2];
    const float* Wv = (const float*)d_in[3];
    const float* Wo = (const float*)d_in[4];
    float* out = (float*)d_out;

    float *q, *k, *v, *a;
    cudaGetSymbolAddress((void**)&q, g_q);
    cudaGetSymbolAddress((void**)&k, g_k);
    cudaGetSymbolAddress((void**)&v, g_v);
    cudaGetSymbolAddress((void**)&a, g_a);

    const int gemm_smem = (2 * 128 * GA + 2 * 32 * GB) * 4;  // 71680
    cudaFuncSetAttribute(gemm_tf32,
                         cudaFuncAttributeMaxDynamicSharedMemorySize, gemm_smem);
    const int attn_smem =
        (128 * QS_S + 2 * 64 * KS_S + 128 * PS_S + 512) * 4;
    cudaFuncSetAttribute(attn_tf32,
                         cudaFuncAttributeMaxDynamicSharedMemorySize, attn_smem);

    // fused QKV projection
    gemm_tf32<<<dim3(DD / 128, MTOT / 128, 3), 256, gemm_smem>>>(
        x, Wq, Wk, Wv, q, k, v, MTOT, DD, DD);

    attn_tf32<<<dim3(NN / 128, BB * HH), 512, attn_smem>>>(q, k, v, a);

    // output projection
    gemm_tf32<<<dim3(DD / 128, MTOT / 128, 1), 256, gemm_smem>>>(
        a, Wo, Wo, Wo, out, out, out, MTOT, DD, DD);
}

// round 7
// speedup vs baseline: 16.2041x; 2.0550x over previous
#include <cuda_runtime.h>
#include <cuda_fp16.h>
#include <cstdint>

#define BB 4
#define NN 2048
#define DD 1024
#define MTOT (BB * NN)  // 8192

// fp16 scratch (allocation-free rule: __device__ globals)
static __device__ __align__(256) half g_xh[MTOT * DD];
static __device__ __align__(256) half g_wqh[DD * DD];
static __device__ __align__(256) half g_wkh[DD * DD];
static __device__ __align__(256) half g_wvh[DD * DD];
static __device__ __align__(256) half g_woh[DD * DD];
static __device__ __align__(256) half g_q[MTOT * DD];
static __device__ __align__(256) half g_k[MTOT * DD];
static __device__ __align__(256) half g_v[MTOT * DD];
static __device__ __align__(256) half g_a[MTOT * DD];

// ---------------------------------------------------------------------------
__device__ __forceinline__ void mma_f16(float d[4], const uint32_t a[4],
                                        const uint32_t b[2]) {
    asm volatile(
        "mma.sync.aligned.m16n8k16.row.col.f32.f16.f16.f32 "
        "{%0,%1,%2,%3}, {%4,%5,%6,%7}, {%8,%9}, {%0,%1,%2,%3};"
        : "+f"(d[0]), "+f"(d[1]), "+f"(d[2]), "+f"(d[3])
        : "r"(a[0]), "r"(a[1]), "r"(a[2]), "r"(a[3]), "r"(b[0]), "r"(b[1]));
}

// Transposed b16 ldmatrix: source row-major [k][n], yields col-major B frags.
__device__ __forceinline__ void ldsm2t(uint32_t& r0, uint32_t& r1,
                                       const half* p) {
    uint32_t sa = (uint32_t)__cvta_generic_to_shared(p);
    asm volatile("ldmatrix.sync.aligned.m8n8.x2.trans.shared.b16 {%0,%1}, [%2];"
                 : "=r"(r0), "=r"(r1) : "r"(sa));
}

__device__ __forceinline__ void cp16(void* smem, const void* g) {
    uint32_t s = (uint32_t)__cvta_generic_to_shared(smem);
    asm volatile("cp.async.ca.shared.global [%0], [%1], 16;" :: "r"(s), "l"(g));
}

// ---------------------------------------------------------------------------
// fp32 -> fp16 convert (with optional scale folded in)
// ---------------------------------------------------------------------------
__global__ void f2h_kernel(const float* __restrict__ in, half* __restrict__ out,
                           int n4, float s)
{
    int i = blockIdx.x * blockDim.x + threadIdx.x;
    int stride = gridDim.x * blockDim.x;
    for (; i < n4; i += stride) {
        float4 f = ((const float4*)in)[i];
        ((half2*)out)[2 * i]     = __floats2half2_rn(f.x * s, f.y * s);
        ((half2*)out)[2 * i + 1] = __floats2half2_rn(f.z * s, f.w * s);
    }
}

// ---------------------------------------------------------------------------
// fp16 GEMM: C[M,N] = A[M,K] @ B[K,N]. Block 128x128, BK=32, 256 thr,
// 2-stage cp.async. A frags: direct half2 LDS (pitch 40 halves, conflict-free).
// B frags: ldmatrix.x2.trans from row-major [k][n] tile (pitch 136 halves).
// smem: 2*(128*40 + 32*136)*2 = 37888 B -> 2 blocks/SM.
// ---------------------------------------------------------------------------
#define GAH 40    // As pitch in halves
#define GBH 136   // Bs pitch in halves

template <bool HOUT>
__global__ __launch_bounds__(256, 2) void gemm_f16(
    const half* __restrict__ A,
    const half* __restrict__ W0, const half* __restrict__ W1,
    const half* __restrict__ W2,
    void* __restrict__ C0, void* __restrict__ C1, void* __restrict__ C2,
    int M, int N, int K)
{
    const half* Bm = (blockIdx.z == 0) ? W0 : (blockIdx.z == 1) ? W1 : W2;
    void* Cv = (blockIdx.z == 0) ? C0 : (blockIdx.z == 1) ? C1 : C2;

    extern __shared__ half gsm[];
    half* As = gsm;                  // [2][128*GAH]
    half* Bs = gsm + 2 * 128 * GAH;  // [2][32*GBH]

    const int tid = threadIdx.x;
    const int lane = tid & 31;
    const int wid = tid >> 5;
    const int wm = (wid & 1) * 64;
    const int wn = (wid >> 1) * 32;
    const int g  = lane >> 2;
    const int c4 = lane & 3;
    const int l16 = lane & 15;
    const int rowBase = blockIdx.y * 128;
    const int colBase = blockIdx.x * 128;

    float acc[4][4][4] = {};

    auto load_stage = [&](int kt, int bufi) {
        half* Asb = As + bufi * 128 * GAH;
        half* Bsb = Bs + bufi * 32 * GBH;
#pragma unroll
        for (int j = 0; j < 2; j++) {
            int ch = tid + 256 * j;           // 512 chunks of 8 halves
            int r = ch >> 2, c = (ch & 3) * 8;
            cp16(&Asb[r * GAH + c], A + (size_t)(rowBase + r) * K + kt + c);
        }
#pragma unroll
        for (int j = 0; j < 2; j++) {
            int ch = tid + 256 * j;
            int kr = ch >> 4, c = (ch & 15) * 8;
            cp16(&Bsb[kr * GBH + c],
                 Bm + (size_t)(kt + kr) * N + colBase + c);
        }
    };

    load_stage(0, 0);
    asm volatile("cp.async.commit_group;" ::: "memory");

    const int T = K / 32;
    for (int t = 0; t < T; t++) {
        if (t + 1 < T) {
            load_stage((t + 1) * 32, (t + 1) & 1);
            asm volatile("cp.async.commit_group;" ::: "memory");
            asm volatile("cp.async.wait_group 1;" ::: "memory");
        } else {
            asm volatile("cp.async.wait_group 0;" ::: "memory");
        }
        __syncthreads();

        const half* Asb = As + (t & 1) * 128 * GAH;
        const half* Bsb = Bs + (t & 1) * 32 * GBH;
        const uint32_t* As2 = (const uint32_t*)Asb;  // half2 view, pitch 20

#pragma unroll
        for (int ks = 0; ks < 2; ks++) {  // k-steps of 16 within BK=32
            uint32_t a[4][4], b[4][2];
#pragma unroll
            for (int mt = 0; mt < 4; mt++) {
                int r = wm + mt * 16 + g;
                a[mt][0] = As2[r * 20 + ks * 8 + c4];
                a[mt][1] = As2[(r + 8) * 20 + ks * 8 + c4];
                a[mt][2] = As2[r * 20 + ks * 8 + 4 + c4];
                a[mt][3] = As2[(r + 8) * 20 + ks * 8 + 4 + c4];
            }
#pragma unroll
            for (int nt = 0; nt < 4; nt++)
                ldsm2t(b[nt][0], b[nt][1],
                       &Bsb[(ks * 16 + l16) * GBH + wn + nt * 8]);
#pragma unroll
            for (int mt = 0; mt < 4; mt++)
#pragma unroll
                for (int nt = 0; nt < 4; nt++)
                    mma_f16(acc[mt][nt], a[mt], b[nt]);
        }
        __syncthreads();
    }

#pragma unroll
    for (int mt = 0; mt < 4; mt++) {
        int r0 = rowBase + wm + mt * 16 + g;
#pragma unroll
        for (int nt = 0; nt < 4; nt++) {
            int cc = colBase + wn + nt * 8 + 2 * c4;
            if (HOUT) {
                half* C = (half*)Cv;
                *(half2*)(C + (size_t)r0 * N + cc) =
                    __floats2half2_rn(acc[mt][nt][0], acc[mt][nt][1]);
                *(half2*)(C + (size_t)(r0 + 8) * N + cc) =
                    __floats2half2_rn(acc[mt][nt][2], acc[mt][nt][3]);
            } else {
                float* C = (float*)Cv;
                *(float2*)(C + (size_t)r0 * N + cc) =
                    make_float2(acc[mt][nt][0], acc[mt][nt][1]);
                *(float2*)(C + (size_t)(r0 + 8) * N + cc) =
                    make_float2(acc[mt][nt][2], acc[mt][nt][3]);
            }
        }
    }
}

// ---------------------------------------------------------------------------
// fp16 flash attention. 512 threads. Block = 128 q-rows of one (b,h).
// KV tile 64, double-buffered via cp.async. Q pre-scaled (folded into Wq).
// Warp (r2 = wid&7, c2 = wid>>3): S-phase rows 16r2.. x kv [32c2,32c2+32);
// PV rows 16r2.. x d [64c2, 64c2+64). K b-frags: direct half2 LDS.
// V b-frags: ldmatrix.x2.trans (no transpose staging needed).
// smem (halves): Qs 128*136 | Ks 2*64*136 | Vs 2*64*136 | Ps 128*72
//   + Mred/Lred 512 floats = 124928 B.
// ---------------------------------------------------------------------------
#define QP 136        // Qs/Ks/Vs pitch (halves)
#define PP 72         // Ps pitch (halves)
#define KVSZ (64 * QP)

__global__ __launch_bounds__(512, 1) void attn_f16(
    const half* __restrict__ Q, const half* __restrict__ K,
    const half* __restrict__ V, half* __restrict__ O)
{
    extern __shared__ half smh[];
    half* Qs = smh;                    // 128*136
    half* Ks = Qs + 128 * QP;          // [2][64*136]
    half* Vs = Ks + 2 * KVSZ;          // [2][64*136]
    half* Ps = Vs + 2 * KVSZ;          // 128*72
    float* Mred = (float*)(Ps + 128 * PP);  // [2][128]
    float* Lred = Mred + 256;               // [2][128]

    const int tid = threadIdx.x;
    const int lane = tid & 31;
    const int wid = tid >> 5;
    const int r2 = wid & 7;
    const int c2 = wid >> 3;
    const int g  = lane >> 2;
    const int c4 = lane & 3;
    const int l16 = lane & 15;
    const int qt = blockIdx.x;
    const int bh = blockIdx.y;
    const int b = bh >> 3;
    const int h = bh & 7;

    const int q0 = r2 * 16 + g;
    const int q1 = q0 + 8;

    const size_t headOff = (size_t)b * NN * DD + (size_t)h * 128;
    const half* Qp = Q + headOff + (size_t)(qt * 128) * DD;
    const half* Kp = K + headOff;
    const half* Vp = V + headOff;

    auto load_kv = [&](int kt, int bufi) {
#pragma unroll
        for (int j = 0; j < 2; j++) {
            int ch = tid + 512 * j;         // 1024 chunks of 8 halves
            int r = ch >> 4, c = (ch & 15) * 8;
            const size_t go = (size_t)(kt * 64 + r) * DD + c;
            cp16(&Ks[bufi * KVSZ + r * QP + c], Kp + go);
            cp16(&Vs[bufi * KVSZ + r * QP + c], Vp + go);
        }
    };

    // Q tile: 2048 chunks of 8 halves
#pragma unroll
    for (int j = 0; j < 4; j++) {
        int ch = tid + 512 * j;
        int r = ch >> 4, c = (ch & 15) * 8;
        cp16(&Qs[r * QP + c], Qp + (size_t)r * DD + c);
    }
    load_kv(0, 0);
    asm volatile("cp.async.commit_group;" ::: "memory");

    float o[8][4] = {};
    float m_lo = -1e30f, m_hi = -1e30f, l_lo = 0.f, l_hi = 0.f;
    const uint32_t* Qs2 = (const uint32_t*)Qs;   // pitch 68 half2

    for (int kt = 0; kt < 32; kt++) {
        asm volatile("cp.async.wait_group 0;" ::: "memory");
        __syncthreads();  // tile kt visible; prev-iter reads complete
        if (kt + 1 < 32) {
            load_kv(kt + 1, (kt + 1) & 1);
            asm volatile("cp.async.commit_group;" ::: "memory");
        }
        const uint32_t* Kb2 = (const uint32_t*)(Ks + (kt & 1) * KVSZ);
        const half* Vb = Vs + (kt & 1) * KVSZ;

        // --- S = Q K^T : warp tile 16 x 32, k = 128 (8 steps of 16) ---
        float s[4][4] = {};
#pragma unroll
        for (int ks = 0; ks < 8; ks++) {
            uint32_t a[4];
            a[0] = Qs2[q0 * 68 + ks * 8 + c4];
            a[1] = Qs2[q1 * 68 + ks * 8 + c4];
            a[2] = Qs2[q0 * 68 + ks * 8 + 4 + c4];
            a[3] = Qs2[q1 * 68 + ks * 8 + 4 + c4];
#pragma unroll
            for (int nt = 0; nt < 4; nt++) {
                uint32_t bf[2];
                int n = c2 * 32 + nt * 8 + g;
                bf[0] = Kb2[n * 68 + ks * 8 + c4];
                bf[1] = Kb2[n * 68 + ks * 8 + 4 + c4];
                mma_f16(s[nt], a, bf);
            }
        }

        // --- warp-local row max ---
        float pm_lo = -1e30f, pm_hi = -1e30f;
#pragma unroll
        for (int nt = 0; nt < 4; nt++) {
            pm_lo = fmaxf(pm_lo, fmaxf(s[nt][0], s[nt][1]));
            pm_hi = fmaxf(pm_hi, fmaxf(s[nt][2], s[nt][3]));
        }
        pm_lo = fmaxf(pm_lo, __shfl_xor_sync(0xffffffffu, pm_lo, 1));
        pm_lo = fmaxf(pm_lo, __shfl_xor_sync(0xffffffffu, pm_lo, 2));
        pm_hi = fmaxf(pm_hi, __shfl_xor_sync(0xffffffffu, pm_hi, 1));
        pm_hi = fmaxf(pm_hi, __shfl_xor_sync(0xffffffffu, pm_hi, 2));
        if (c4 == 0) {
            Mred[c2 * 128 + q0] = pm_lo;
            Mred[c2 * 128 + q1] = pm_hi;
        }
        __syncthreads();

        float mnew_lo = fmaxf(m_lo, fmaxf(Mred[q0], Mred[128 + q0]));
        float mnew_hi = fmaxf(m_hi, fmaxf(Mred[q1], Mred[128 + q1]));
        float al_lo = __expf(m_lo - mnew_lo);
        float al_hi = __expf(m_hi - mnew_hi);
        m_lo = mnew_lo;
        m_hi = mnew_hi;

        float sum_lo = 0.f, sum_hi = 0.f;
#pragma unroll
        for (int nt = 0; nt < 4; nt++) {
            float p0 = __expf(s[nt][0] - mnew_lo);
            float p1 = __expf(s[nt][1] - mnew_lo);
            float p2 = __expf(s[nt][2] - mnew_hi);
            float p3 = __expf(s[nt][3] - mnew_hi);
            sum_lo += p0 + p1;
            sum_hi += p2 + p3;
            int cc = c2 * 32 + nt * 8 + 2 * c4;
            *(half2*)&Ps[q0 * PP + cc] = __floats2half2_rn(p0, p1);
            *(half2*)&Ps[q1 * PP + cc] = __floats2half2_rn(p2, p3);
        }
        sum_lo += __shfl_xor_sync(0xffffffffu, sum_lo, 1);
        sum_lo += __shfl_xor_sync(0xffffffffu, sum_lo, 2);
        sum_hi += __shfl_xor_sync(0xffffffffu, sum_hi, 1);
        sum_hi += __shfl_xor_sync(0xffffffffu, sum_hi, 2);
        if (c4 == 0) {
            Lred[c2 * 128 + q0] = sum_lo;
            Lred[c2 * 128 + q1] = sum_hi;
        }

#pragma unroll
        for (int nt = 0; nt < 8; nt++) {
            o[nt][0] *= al_lo;
            o[nt][1] *= al_lo;
            o[nt][2] *= al_hi;
            o[nt][3] *= al_hi;
        }
        __syncthreads();  // Ps + Lred visible

        l_lo = l_lo * al_lo + Lred[q0] + Lred[128 + q0];
        l_hi = l_hi * al_hi + Lred[q1] + Lred[128 + q1];

        // --- O += P V : warp tile 16 rows x 64 d-cols, k = 64 (4 steps) ---
        const uint32_t* Ps2 = (const uint32_t*)Ps;  // pitch 36 half2
#pragma unroll
        for (int ks = 0; ks < 4; ks++) {
            uint32_t a[4];
            a[0] = Ps2[q0 * 36 + ks * 8 + c4];
            a[1] = Ps2[q1 * 36 + ks * 8 + c4];
            a[2] = Ps2[q0 * 36 + ks * 8 + 4 + c4];
            a[3] = Ps2[q1 * 36 + ks * 8 + 4 + c4];
#pragma unroll
            for (int nt = 0; nt < 8; nt++) {
                uint32_t bf[2];
                ldsm2t(bf[0], bf[1],
                       &Vb[(ks * 16 + l16) * QP + c2 * 64 + nt * 8]);
                mma_f16(o[nt], a, bf);
            }
        }
    }

    // --- epilogue ---
    float inv_lo = 1.f / l_lo;
    float inv_hi = 1.f / l_hi;
    half* Op = O + headOff + (size_t)(qt * 128) * DD;
#pragma unroll
    for (int nt = 0; nt < 8; nt++) {
        int cc = c2 * 64 + nt * 8 + 2 * c4;
        *(half2*)(Op + (size_t)q0 * DD + cc) =
            __floats2half2_rn(o[nt][0] * inv_lo, o[nt][1] * inv_lo);
        *(half2*)(Op + (size_t)q1 * DD + cc) =
            __floats2half2_rn(o[nt][2] * inv_hi, o[nt][3] * inv_hi);
    }
}

// ---------------------------------------------------------------------------
extern "C" void kernel_launch(void* const* d_in, const int* in_sizes, int n_in,
                              void* d_out, int out_size)
{
    const float* x  = (const float*)d_in[0];
    const float* Wq = (const float*)d_in[1];
    const float* Wk = (const float*)d_in[2];
    const float* Wv = (const float*)d_in[3];
    const float* Wo = (const float*)d_in[4];
    float* out = (float*)d_out;

    half *xh, *wqh, *wkh, *wvh, *woh, *q, *k, *v, *a;
    cudaGetSymbolAddress((void**)&xh,  g_xh);
    cudaGetSymbolAddress((void**)&wqh, g_wqh);
    cudaGetSymbolAddress((void**)&wkh, g_wkh);
    cudaGetSymbolAddress((void**)&wvh, g_wvh);
    cudaGetSymbolAddress((void**)&woh, g_woh);
    cudaGetSymbolAddress((void**)&q, g_q);
    cudaGetSymbolAddress((void**)&k, g_k);
    cudaGetSymbolAddress((void**)&v, g_v);
    cudaGetSymbolAddress((void**)&a, g_a);

    const float scale = 0.08838834764831845f;  // 1/sqrt(128) folded into Wq

    // fp32 -> fp16 converts
    f2h_kernel<<<2048, 256>>>(x,  xh,  MTOT * DD / 4, 1.0f);
    f2h_kernel<<<512,  256>>>(Wq, wqh, DD * DD / 4, scale);
    f2h_kernel<<<512,  256>>>(Wk, wkh, DD * DD / 4, 1.0f);
    f2h_kernel<<<512,  256>>>(Wv, wvh, DD * DD / 4, 1.0f);
    f2h_kernel<<<512,  256>>>(Wo, woh, DD * DD / 4, 1.0f);

    const int gemm_smem = (2 * 128 * GAH + 2 * 32 * GBH) * 2;  // 37888
    cudaFuncSetAttribute(gemm_f16<true>,
                         cudaFuncAttributeMaxDynamicSharedMemorySize, gemm_smem);
    cudaFuncSetAttribute(gemm_f16<false>,
                         cudaFuncAttributeMaxDynamicSharedMemorySize, gemm_smem);
    const int attn_smem =
        (128 * QP + 4 * KVSZ + 128 * PP) * 2 + 512 * 4;  // 124928
    cudaFuncSetAttribute(attn_f16,
                         cudaFuncAttributeMaxDynamicSharedMemorySize, attn_smem);

    // fused QKV projection (half out)
    gemm_f16<true><<<dim3(DD / 128, MTOT / 128, 3), 256, gemm_smem>>>(
        xh, wqh, wkh, wvh, q, k, v, MTOT, DD, DD);

    attn_f16<<<dim3(NN / 128, BB * 8), 512, attn_smem>>>(q, k, v, a);

    // output projection (float out)
    gemm_f16<false><<<dim3(DD / 128, MTOT / 128, 1), 256, gemm_smem>>>(
        a, woh, woh, woh, out, out, out, MTOT, DD, DD);
}

// round 10
// speedup vs baseline: 17.6002x; 1.0862x over previous
#include <cuda_runtime.h>
#include <cuda_fp16.h>
#include <cstdint>

#define BB 4
#define NN 2048
#define DD 1024
#define MTOT (BB * NN)  // 8192

// fp16 scratch (allocation-free rule: __device__ globals)
static __device__ __align__(256) half g_xh[MTOT * DD];
static __device__ __align__(256) half g_wqh[DD * DD];
static __device__ __align__(256) half g_wkh[DD * DD];
static __device__ __align__(256) half g_wvh[DD * DD];
static __device__ __align__(256) half g_woh[DD * DD];
static __device__ __align__(256) half g_q[MTOT * DD];
static __device__ __align__(256) half g_k[MTOT * DD];
static __device__ __align__(256) half g_v[MTOT * DD];
static __device__ __align__(256) half g_a[MTOT * DD];

// ---------------------------------------------------------------------------
__device__ __forceinline__ void mma_f16(float d[4], const uint32_t a[4],
                                        const uint32_t b[2]) {
    asm volatile(
        "mma.sync.aligned.m16n8k16.row.col.f32.f16.f16.f32 "
        "{%0,%1,%2,%3}, {%4,%5,%6,%7}, {%8,%9}, {%0,%1,%2,%3};"
        : "+f"(d[0]), "+f"(d[1]), "+f"(d[2]), "+f"(d[3])
        : "r"(a[0]), "r"(a[1]), "r"(a[2]), "r"(a[3]), "r"(b[0]), "r"(b[1]));
}

__device__ __forceinline__ void ldsm4(uint32_t& m0, uint32_t& m1, uint32_t& m2,
                                      uint32_t& m3, const half* p) {
    uint32_t sa = (uint32_t)__cvta_generic_to_shared(p);
    asm volatile(
        "ldmatrix.sync.aligned.m8n8.x4.shared.b16 {%0,%1,%2,%3}, [%4];"
        : "=r"(m0), "=r"(m1), "=r"(m2), "=r"(m3) : "r"(sa));
}

__device__ __forceinline__ void ldsm4t(uint32_t& m0, uint32_t& m1, uint32_t& m2,
                                       uint32_t& m3, const half* p) {
    uint32_t sa = (uint32_t)__cvta_generic_to_shared(p);
    asm volatile(
        "ldmatrix.sync.aligned.m8n8.x4.trans.shared.b16 {%0,%1,%2,%3}, [%4];"
        : "=r"(m0), "=r"(m1), "=r"(m2), "=r"(m3) : "r"(sa));
}

__device__ __forceinline__ void cp16(void* smem, const void* g) {
    uint32_t s = (uint32_t)__cvta_generic_to_shared(smem);
    asm volatile("cp.async.ca.shared.global [%0], [%1], 16;" :: "r"(s), "l"(g));
}

// ---------------------------------------------------------------------------
// fp32 -> fp16 convert (optional scale folded in)
// ---------------------------------------------------------------------------
__global__ void f2h_kernel(const float* __restrict__ in, half* __restrict__ out,
                           int n4, float s)
{
    int i = blockIdx.x * blockDim.x + threadIdx.x;
    int stride = gridDim.x * blockDim.x;
    for (; i < n4; i += stride) {
        float4 f = ((const float4*)in)[i];
        ((half2*)out)[2 * i]     = __floats2half2_rn(f.x * s, f.y * s);
        ((half2*)out)[2 * i + 1] = __floats2half2_rn(f.z * s, f.w * s);
    }
}

// ---------------------------------------------------------------------------
// fp16 GEMM: C[M,N] = A[M,K] @ B[K,N]. Block 128x128, BK=32, 256 thr,
// 2-stage cp.async. A frags: ldmatrix.x4 (row-major [m][k], pitch 40 halves).
// B frags: ldmatrix.x4.trans (row-major [k][n], pitch 136 halves).
// ---------------------------------------------------------------------------
#define GAH 40
#define GBH 136

template <bool HOUT>
__global__ __launch_bounds__(256, 2) void gemm_f16(
    const half* __restrict__ A,
    const half* __restrict__ W0, const half* __restrict__ W1,
    const half* __restrict__ W2,
    void* __restrict__ C0, void* __restrict__ C1, void* __restrict__ C2,
    int M, int N, int K)
{
    const half* Bm = (blockIdx.z == 0) ? W0 : (blockIdx.z == 1) ? W1 : W2;
    void* Cv = (blockIdx.z == 0) ? C0 : (blockIdx.z == 1) ? C1 : C2;

    extern __shared__ half gsm[];
    half* As = gsm;                  // [2][128*GAH]
    half* Bs = gsm + 2 * 128 * GAH;  // [2][32*GBH]

    const int tid = threadIdx.x;
    const int lane = tid & 31;
    const int wid = tid >> 5;
    const int wm = (wid & 1) * 64;
    const int wn = (wid >> 1) * 32;
    const int g  = lane >> 2;
    const int c4 = lane & 3;
    const int rowBase = blockIdx.y * 128;
    const int colBase = blockIdx.x * 128;

    // ldmatrix lane-offset maps
    const int arow = (lane & 7) + ((lane >> 3) & 1) * 8;  // A / trans-B row
    const int acol = (lane >> 4) * 8;                     // A / trans-B col

    float acc[4][4][4] = {};

    auto load_stage = [&](int kt, int bufi) {
        half* Asb = As + bufi * 128 * GAH;
        half* Bsb = Bs + bufi * 32 * GBH;
#pragma unroll
        for (int j = 0; j < 2; j++) {
            int ch = tid + 256 * j;
            int r = ch >> 2, c = (ch & 3) * 8;
            cp16(&Asb[r * GAH + c], A + (size_t)(rowBase + r) * K + kt + c);
        }
#pragma unroll
        for (int j = 0; j < 2; j++) {
            int ch = tid + 256 * j;
            int kr = ch >> 4, c = (ch & 15) * 8;
            cp16(&Bsb[kr * GBH + c],
                 Bm + (size_t)(kt + kr) * N + colBase + c);
        }
    };

    load_stage(0, 0);
    asm volatile("cp.async.commit_group;" ::: "memory");

    const int T = K / 32;
    for (int t = 0; t < T; t++) {
        if (t + 1 < T) {
            load_stage((t + 1) * 32, (t + 1) & 1);
            asm volatile("cp.async.commit_group;" ::: "memory");
            asm volatile("cp.async.wait_group 1;" ::: "memory");
        } else {
            asm volatile("cp.async.wait_group 0;" ::: "memory");
        }
        __syncthreads();

        const half* Asb = As + (t & 1) * 128 * GAH;
        const half* Bsb = Bs + (t & 1) * 32 * GBH;

#pragma unroll
        for (int ks = 0; ks < 2; ks++) {
            uint32_t a[4][4], b[4][2];
#pragma unroll
            for (int mt = 0; mt < 4; mt++)
                ldsm4(a[mt][0], a[mt][1], a[mt][2], a[mt][3],
                      Asb + (wm + mt * 16 + arow) * GAH + ks * 16 + acol);
#pragma unroll
            for (int ntp = 0; ntp < 2; ntp++)
                ldsm4t(b[2 * ntp][0], b[2 * ntp][1],
                       b[2 * ntp + 1][0], b[2 * ntp + 1][1],
                       Bsb + (ks * 16 + arow) * GBH + wn + ntp * 16 + acol);
#pragma unroll
            for (int mt = 0; mt < 4; mt++)
#pragma unroll
                for (int nt = 0; nt < 4; nt++)
                    mma_f16(acc[mt][nt], a[mt], b[nt]);
        }
        __syncthreads();
    }

#pragma unroll
    for (int mt = 0; mt < 4; mt++) {
        int r0 = rowBase + wm + mt * 16 + g;
#pragma unroll
        for (int nt = 0; nt < 4; nt++) {
            int cc = colBase + wn + nt * 8 + 2 * c4;
            if (HOUT) {
                half* C = (half*)Cv;
                *(half2*)(C + (size_t)r0 * N + cc) =
                    __floats2half2_rn(acc[mt][nt][0], acc[mt][nt][1]);
                *(half2*)(C + (size_t)(r0 + 8) * N + cc) =
                    __floats2half2_rn(acc[mt][nt][2], acc[mt][nt][3]);
            } else {
                float* C = (float*)Cv;
                *(float2*)(C + (size_t)r0 * N + cc) =
                    make_float2(acc[mt][nt][0], acc[mt][nt][1]);
                *(float2*)(C + (size_t)(r0 + 8) * N + cc) =
                    make_float2(acc[mt][nt][2], acc[mt][nt][3]);
            }
        }
    }
}

// ---------------------------------------------------------------------------
// fp16 flash attention. 512 threads. Block = 128 q-rows of one (b,h).
// KV tile 64, double-buffered cp.async. Q pre-scaled (folded into Wq).
// Warp (r2 = wid&7, c2 = wid>>3): S rows 16r2.. x kv [32c2,+32);
// PV rows 16r2.. x d [64c2,+64).
// Softmax couples only the two c2-warps of a row group -> NAMED pair barrier
// (bar.sync 1+r2, 64) instead of block-wide syncs. Only the KV buffer swap
// remains block-wide. All fragments via ldmatrix.x4.
// ---------------------------------------------------------------------------
#define QP 136
#define PP 72
#define KVSZ (64 * QP)

__global__ __launch_bounds__(512, 1) void attn_f16(
    const half* __restrict__ Q, const half* __restrict__ K,
    const half* __restrict__ V, half* __restrict__ O)
{
    extern __shared__ half smh[];
    half* Qs = smh;                    // 128*136
    half* Ks = Qs + 128 * QP;          // [2][64*136]
    half* Vs = Ks + 2 * KVSZ;          // [2][64*136]
    half* Ps = Vs + 2 * KVSZ;          // 128*72
    float* Mred = (float*)(Ps + 128 * PP);  // [2][128]
    float* Lred = Mred + 256;               // [2][128]

    const int tid = threadIdx.x;
    const int lane = tid & 31;
    const int wid = tid >> 5;
    const int r2 = wid & 7;
    const int c2 = wid >> 3;
    const int g  = lane >> 2;
    const int c4 = lane & 3;
    const int qt = blockIdx.x;
    const int bh = blockIdx.y;
    const int b = bh >> 3;
    const int h = bh & 7;

    const int q0 = r2 * 16 + g;
    const int q1 = q0 + 8;

    // ldmatrix lane-offset maps
    const int arow = (lane & 7) + ((lane >> 3) & 1) * 8;  // A-frag / trans-B
    const int acol = (lane >> 4) * 8;
    const int brow = (lane & 7) + ((lane >> 4) & 1) * 8;  // non-trans B (K)
    const int bcol = ((lane >> 3) & 1) * 8;

    const size_t headOff = (size_t)b * NN * DD + (size_t)h * 128;
    const half* Qp = Q + headOff + (size_t)(qt * 128) * DD;
    const half* Kp = K + headOff;
    const half* Vp = V + headOff;

    auto load_kv = [&](int kt, int bufi) {
#pragma unroll
        for (int j = 0; j < 2; j++) {
            int ch = tid + 512 * j;
            int r = ch >> 4, c = (ch & 15) * 8;
            const size_t go = (size_t)(kt * 64 + r) * DD + c;
            cp16(&Ks[bufi * KVSZ + r * QP + c], Kp + go);
            cp16(&Vs[bufi * KVSZ + r * QP + c], Vp + go);
        }
    };

#pragma unroll
    for (int j = 0; j < 4; j++) {
        int ch = tid + 512 * j;
        int r = ch >> 4, c = (ch & 15) * 8;
        cp16(&Qs[r * QP + c], Qp + (size_t)r * DD + c);
    }
    load_kv(0, 0);
    asm volatile("cp.async.commit_group;" ::: "memory");

    float o[8][4] = {};
    float m_lo = -1e30f, m_hi = -1e30f, l_lo = 0.f, l_hi = 0.f;

    for (int kt = 0; kt < 32; kt++) {
        asm volatile("cp.async.wait_group 0;" ::: "memory");
        __syncthreads();  // tile kt visible; all prev-iter smem reads complete
        if (kt + 1 < 32) {
            load_kv(kt + 1, (kt + 1) & 1);
            asm volatile("cp.async.commit_group;" ::: "memory");
        }
        const half* Kb = Ks + (kt & 1) * KVSZ;
        const half* Vb = Vs + (kt & 1) * KVSZ;

        // --- S = Q K^T : warp tile 16 x 32, k = 128 ---
        float s[4][4] = {};
#pragma unroll
        for (int ks = 0; ks < 8; ks++) {
            uint32_t a[4];
            ldsm4(a[0], a[1], a[2], a[3],
                  Qs + (r2 * 16 + arow) * QP + ks * 16 + acol);
#pragma unroll
            for (int ntp = 0; ntp < 2; ntp++) {
                uint32_t bf0[2], bf1[2];
                ldsm4(bf0[0], bf0[1], bf1[0], bf1[1],
                      Kb + (c2 * 32 + ntp * 16 + brow) * QP + ks * 16 + bcol);
                mma_f16(s[2 * ntp], a, bf0);
                mma_f16(s[2 * ntp + 1], a, bf1);
            }
        }

        // --- warp-local row max ---
        float pm_lo = -1e30f, pm_hi = -1e30f;
#pragma unroll
        for (int nt = 0; nt < 4; nt++) {
            pm_lo = fmaxf(pm_lo, fmaxf(s[nt][0], s[nt][1]));
            pm_hi = fmaxf(pm_hi, fmaxf(s[nt][2], s[nt][3]));
        }
        pm_lo = fmaxf(pm_lo, __shfl_xor_sync(0xffffffffu, pm_lo, 1));
        pm_lo = fmaxf(pm_lo, __shfl_xor_sync(0xffffffffu, pm_lo, 2));
        pm_hi = fmaxf(pm_hi, __shfl_xor_sync(0xffffffffu, pm_hi, 1));
        pm_hi = fmaxf(pm_hi, __shfl_xor_sync(0xffffffffu, pm_hi, 2));
        if (c4 == 0) {
            Mred[c2 * 128 + q0] = pm_lo;
            Mred[c2 * 128 + q1] = pm_hi;
        }
        asm volatile("bar.sync %0, 64;" :: "r"(1 + r2) : "memory");

        float mnew_lo = fmaxf(m_lo, fmaxf(Mred[q0], Mred[128 + q0]));
        float mnew_hi = fmaxf(m_hi, fmaxf(Mred[q1], Mred[128 + q1]));
        float al_lo = __expf(m_lo - mnew_lo);
        float al_hi = __expf(m_hi - mnew_hi);
        m_lo = mnew_lo;
        m_hi = mnew_hi;

        float sum_lo = 0.f, sum_hi = 0.f;
#pragma unroll
        for (int nt = 0; nt < 4; nt++) {
            float p0 = __expf(s[nt][0] - mnew_lo);
            float p1 = __expf(s[nt][1] - mnew_lo);
            float p2 = __expf(s[nt][2] - mnew_hi);
            float p3 = __expf(s[nt][3] - mnew_hi);
            sum_lo += p0 + p1;
            sum_hi += p2 + p3;
            int cc = c2 * 32 + nt * 8 + 2 * c4;
            *(half2*)&Ps[q0 * PP + cc] = __floats2half2_rn(p0, p1);
            *(half2*)&Ps[q1 * PP + cc] = __floats2half2_rn(p2, p3);
        }
        sum_lo += __shfl_xor_sync(0xffffffffu, sum_lo, 1);
        sum_lo += __shfl_xor_sync(0xffffffffu, sum_lo, 2);
        sum_hi += __shfl_xor_sync(0xffffffffu, sum_hi, 1);
        sum_hi += __shfl_xor_sync(0xffffffffu, sum_hi, 2);
        if (c4 == 0) {
            Lred[c2 * 128 + q0] = sum_lo;
            Lred[c2 * 128 + q1] = sum_hi;
        }

#pragma unroll
        for (int nt = 0; nt < 8; nt++) {
            o[nt][0] *= al_lo;
            o[nt][1] *= al_lo;
            o[nt][2] *= al_hi;
            o[nt][3] *= al_hi;
        }
        asm volatile("bar.sync %0, 64;" :: "r"(1 + r2) : "memory");

        l_lo = l_lo * al_lo + Lred[q0] + Lred[128 + q0];
        l_hi = l_hi * al_hi + Lred[q1] + Lred[128 + q1];

        // --- O += P V : warp tile 16 rows x 64 d-cols, k = 64 ---
#pragma unroll
        for (int ks = 0; ks < 4; ks++) {
            uint32_t a[4];
            ldsm4(a[0], a[1], a[2], a[3],
                  Ps + (r2 * 16 + arow) * PP + ks * 16 + acol);
#pragma unroll
            for (int ntp = 0; ntp < 4; ntp++) {
                uint32_t bf0[2], bf1[2];
                ldsm4t(bf0[0], bf0[1], bf1[0], bf1[1],
                       Vb + (ks * 16 + arow) * QP + c2 * 64 + ntp * 16 + acol);
                mma_f16(o[2 * ntp], a, bf0);
                mma_f16(o[2 * ntp + 1], a, bf1);
            }
        }
    }

    // --- epilogue ---
    float inv_lo = 1.f / l_lo;
    float inv_hi = 1.f / l_hi;
    half* Op = O + headOff + (size_t)(qt * 128) * DD;
#pragma unroll
    for (int nt = 0; nt < 8; nt++) {
        int cc = c2 * 64 + nt * 8 + 2 * c4;
        *(half2*)(Op + (size_t)q0 * DD + cc) =
            __floats2half2_rn(o[nt][0] * inv_lo, o[nt][1] * inv_lo);
        *(half2*)(Op + (size_t)q1 * DD + cc) =
            __floats2half2_rn(o[nt][2] * inv_hi, o[nt][3] * inv_hi);
    }
}

// ---------------------------------------------------------------------------
extern "C" void kernel_launch(void* const* d_in, const int* in_sizes, int n_in,
                              void* d_out, int out_size)
{
    const float* x  = (const float*)d_in[0];
    const float* Wq = (const float*)d_in[1];
    const float* Wk = (const float*)d_in[2];
    const float* Wv = (const float*)d_in[3];
    const float* Wo = (const float*)d_in[4];
    float* out = (float*)d_out;

    half *xh, *wqh, *wkh, *wvh, *woh, *q, *k, *v, *a;
    cudaGetSymbolAddress((void**)&xh,  g_xh);
    cudaGetSymbolAddress((void**)&wqh, g_wqh);
    cudaGetSymbolAddress((void**)&wkh, g_wkh);
    cudaGetSymbolAddress((void**)&wvh, g_wvh);
    cudaGetSymbolAddress((void**)&woh, g_woh);
    cudaGetSymbolAddress((void**)&q, g_q);
    cudaGetSymbolAddress((void**)&k, g_k);
    cudaGetSymbolAddress((void**)&v, g_v);
    cudaGetSymbolAddress((void**)&a, g_a);

    const float scale = 0.08838834764831845f;  // 1/sqrt(128) folded into Wq

    f2h_kernel<<<2048, 256>>>(x,  xh,  MTOT * DD / 4, 1.0f);
    f2h_kernel<<<512,  256>>>(Wq, wqh, DD * DD / 4, scale);
    f2h_kernel<<<512,  256>>>(Wk, wkh, DD * DD / 4, 1.0f);
    f2h_kernel<<<512,  256>>>(Wv, wvh, DD * DD / 4, 1.0f);
    f2h_kernel<<<512,  256>>>(Wo, woh, DD * DD / 4, 1.0f);

    const int gemm_smem = (2 * 128 * GAH + 2 * 32 * GBH) * 2;  // 37888
    cudaFuncSetAttribute(gemm_f16<true>,
                         cudaFuncAttributeMaxDynamicSharedMemorySize, gemm_smem);
    cudaFuncSetAttribute(gemm_f16<false>,
                         cudaFuncAttributeMaxDynamicSharedMemorySize, gemm_smem);
    const int attn_smem = (128 * QP + 4 * KVSZ + 128 * PP) * 2 + 512 * 4;
    cudaFuncSetAttribute(attn_f16,
                         cudaFuncAttributeMaxDynamicSharedMemorySize, attn_smem);

    // fused QKV projection (half out)
    gemm_f16<true><<<dim3(DD / 128, MTOT / 128, 3), 256, gemm_smem>>>(
        xh, wqh, wkh, wvh, q, k, v, MTOT, DD, DD);

    attn_f16<<<dim3(NN / 128, BB * 8), 512, attn_smem>>>(q, k, v, a);

    // output projection (float out)
    gemm_f16<false><<<dim3(DD / 128, MTOT / 128, 1), 256, gemm_smem>>>(
        a, woh, woh, woh, out, out, out, MTOT, DD, DD);
}

// round 12
// speedup vs baseline: 20.2431x; 1.1502x over previous
#include <cuda_runtime.h>
#include <cuda_fp16.h>
#include <cstdint>

#define BB 4
#define NN 2048
#define DD 1024
#define MTOT (BB * NN)  // 8192

// fp16 scratch (allocation-free rule: __device__ globals)
static __device__ __align__(256) half g_xh[MTOT * DD];
static __device__ __align__(256) half g_wqh[DD * DD];
static __device__ __align__(256) half g_wkh[DD * DD];
static __device__ __align__(256) half g_wvh[DD * DD];
static __device__ __align__(256) half g_woh[DD * DD];
static __device__ __align__(256) half g_q[MTOT * DD];
static __device__ __align__(256) half g_k[MTOT * DD];
static __device__ __align__(256) half g_v[MTOT * DD];
static __device__ __align__(256) half g_a[MTOT * DD];

// ---------------------------------------------------------------------------
__device__ __forceinline__ uint32_t h2u(half2 h) {
    return *reinterpret_cast<uint32_t*>(&h);
}

__device__ __forceinline__ void mma_f16(float d[4], const uint32_t a[4],
                                        const uint32_t b[2]) {
    asm volatile(
        "mma.sync.aligned.m16n8k16.row.col.f32.f16.f16.f32 "
        "{%0,%1,%2,%3}, {%4,%5,%6,%7}, {%8,%9}, {%0,%1,%2,%3};"
        : "+f"(d[0]), "+f"(d[1]), "+f"(d[2]), "+f"(d[3])
        : "r"(a[0]), "r"(a[1]), "r"(a[2]), "r"(a[3]), "r"(b[0]), "r"(b[1]));
}

__device__ __forceinline__ void ldsm4(uint32_t& m0, uint32_t& m1, uint32_t& m2,
                                      uint32_t& m3, const half* p) {
    uint32_t sa = (uint32_t)__cvta_generic_to_shared(p);
    asm volatile(
        "ldmatrix.sync.aligned.m8n8.x4.shared.b16 {%0,%1,%2,%3}, [%4];"
        : "=r"(m0), "=r"(m1), "=r"(m2), "=r"(m3) : "r"(sa));
}

__device__ __forceinline__ void ldsm4t(uint32_t& m0, uint32_t& m1, uint32_t& m2,
                                       uint32_t& m3, const half* p) {
    uint32_t sa = (uint32_t)__cvta_generic_to_shared(p);
    asm volatile(
        "ldmatrix.sync.aligned.m8n8.x4.trans.shared.b16 {%0,%1,%2,%3}, [%4];"
        : "=r"(m0), "=r"(m1), "=r"(m2), "=r"(m3) : "r"(sa));
}

__device__ __forceinline__ void cp16(void* smem, const void* g) {
    uint32_t s = (uint32_t)__cvta_generic_to_shared(smem);
    asm volatile("cp.async.ca.shared.global [%0], [%1], 16;" :: "r"(s), "l"(g));
}

// ---------------------------------------------------------------------------
// fp32 -> fp16 convert (optional scale folded in)
// ---------------------------------------------------------------------------
__global__ void f2h_kernel(const float* __restrict__ in, half* __restrict__ out,
                           int n4, float s)
{
    int i = blockIdx.x * blockDim.x + threadIdx.x;
    int stride = gridDim.x * blockDim.x;
    for (; i < n4; i += stride) {
        float4 f = ((const float4*)in)[i];
        ((half2*)out)[2 * i]     = __floats2half2_rn(f.x * s, f.y * s);
        ((half2*)out)[2 * i + 1] = __floats2half2_rn(f.z * s, f.w * s);
    }
}

// ---------------------------------------------------------------------------
// fp16 GEMM (unchanged): block 128x128, BK=32, 256 thr, 2-stage cp.async.
// ---------------------------------------------------------------------------
#define GAH 40
#define GBH 136

template <bool HOUT>
__global__ __launch_bounds__(256, 2) void gemm_f16(
    const half* __restrict__ A,
    const half* __restrict__ W0, const half* __restrict__ W1,
    const half* __restrict__ W2,
    void* __restrict__ C0, void* __restrict__ C1, void* __restrict__ C2,
    int M, int N, int K)
{
    const half* Bm = (blockIdx.z == 0) ? W0 : (blockIdx.z == 1) ? W1 : W2;
    void* Cv = (blockIdx.z == 0) ? C0 : (blockIdx.z == 1) ? C1 : C2;

    extern __shared__ half gsm[];
    half* As = gsm;                  // [2][128*GAH]
    half* Bs = gsm + 2 * 128 * GAH;  // [2][32*GBH]

    const int tid = threadIdx.x;
    const int lane = tid & 31;
    const int wid = tid >> 5;
    const int wm = (wid & 1) * 64;
    const int wn = (wid >> 1) * 32;
    const int g  = lane >> 2;
    const int c4 = lane & 3;
    const int rowBase = blockIdx.y * 128;
    const int colBase = blockIdx.x * 128;

    const int arow = (lane & 7) + ((lane >> 3) & 1) * 8;
    const int acol = (lane >> 4) * 8;

    float acc[4][4][4] = {};

    auto load_stage = [&](int kt, int bufi) {
        half* Asb = As + bufi * 128 * GAH;
        half* Bsb = Bs + bufi * 32 * GBH;
#pragma unroll
        for (int j = 0; j < 2; j++) {
            int ch = tid + 256 * j;
            int r = ch >> 2, c = (ch & 3) * 8;
            cp16(&Asb[r * GAH + c], A + (size_t)(rowBase + r) * K + kt + c);
        }
#pragma unroll
        for (int j = 0; j < 2; j++) {
            int ch = tid + 256 * j;
            int kr = ch >> 4, c = (ch & 15) * 8;
            cp16(&Bsb[kr * GBH + c],
                 Bm + (size_t)(kt + kr) * N + colBase + c);
        }
    };

    load_stage(0, 0);
    asm volatile("cp.async.commit_group;" ::: "memory");

    const int T = K / 32;
    for (int t = 0; t < T; t++) {
        if (t + 1 < T) {
            load_stage((t + 1) * 32, (t + 1) & 1);
            asm volatile("cp.async.commit_group;" ::: "memory");
            asm volatile("cp.async.wait_group 1;" ::: "memory");
        } else {
            asm volatile("cp.async.wait_group 0;" ::: "memory");
        }
        __syncthreads();

        const half* Asb = As + (t & 1) * 128 * GAH;
        const half* Bsb = Bs + (t & 1) * 32 * GBH;

#pragma unroll
        for (int ks = 0; ks < 2; ks++) {
            uint32_t a[4][4], b[4][2];
#pragma unroll
            for (int mt = 0; mt < 4; mt++)
                ldsm4(a[mt][0], a[mt][1], a[mt][2], a[mt][3],
                      Asb + (wm + mt * 16 + arow) * GAH + ks * 16 + acol);
#pragma unroll
            for (int ntp = 0; ntp < 2; ntp++)
                ldsm4t(b[2 * ntp][0], b[2 * ntp][1],
                       b[2 * ntp + 1][0], b[2 * ntp + 1][1],
                       Bsb + (ks * 16 + arow) * GBH + wn + ntp * 16 + acol);
#pragma unroll
            for (int mt = 0; mt < 4; mt++)
#pragma unroll
                for (int nt = 0; nt < 4; nt++)
                    mma_f16(acc[mt][nt], a[mt], b[nt]);
        }
        __syncthreads();
    }

#pragma unroll
    for (int mt = 0; mt < 4; mt++) {
        int r0 = rowBase + wm + mt * 16 + g;
#pragma unroll
        for (int nt = 0; nt < 4; nt++) {
            int cc = colBase + wn + nt * 8 + 2 * c4;
            if (HOUT) {
                half* C = (half*)Cv;
                *(half2*)(C + (size_t)r0 * N + cc) =
                    __floats2half2_rn(acc[mt][nt][0], acc[mt][nt][1]);
                *(half2*)(C + (size_t)(r0 + 8) * N + cc) =
                    __floats2half2_rn(acc[mt][nt][2], acc[mt][nt][3]);
            } else {
                float* C = (float*)Cv;
                *(float2*)(C + (size_t)r0 * N + cc) =
                    make_float2(acc[mt][nt][0], acc[mt][nt][1]);
                *(float2*)(C + (size_t)(r0 + 8) * N + cc) =
                    make_float2(acc[mt][nt][2], acc[mt][nt][3]);
            }
        }
    }
}

// ---------------------------------------------------------------------------
// fp16 flash attention, FA2-style. 256 threads (8 warps), 2 blocks/SM.
// Block = 128 q-rows of one (b,h). KV tile 64, double-buffered cp.async.
// Warp = 16 q-rows x FULL width (64 kv cols in S, 128 d-cols in PV).
// Softmax entirely warp-local; P stays in registers (C-frag -> A-frag).
// smem: Qs 128*136 + Ks 2*64*136 + Vs 2*64*136 halves = 104448 B.
// ---------------------------------------------------------------------------
#define QP 136
#define KVSZ (64 * QP)

__global__ __launch_bounds__(256, 2) void attn_f16(
    const half* __restrict__ Q, const half* __restrict__ K,
    const half* __restrict__ V, half* __restrict__ O)
{
    extern __shared__ half smh[];
    half* Qs = smh;                    // 128*136
    half* Ks = Qs + 128 * QP;          // [2][64*136]
    half* Vs = Ks + 2 * KVSZ;          // [2][64*136]

    const int tid = threadIdx.x;
    const int lane = tid & 31;
    const int wid = tid >> 5;          // 0..7 -> q rows 16*wid..
    const int g  = lane >> 2;
    const int c4 = lane & 3;
    const int qt = blockIdx.x;
    const int bh = blockIdx.y;
    const int b = bh >> 3;
    const int h = bh & 7;

    const int q0 = wid * 16 + g;
    const int q1 = q0 + 8;

    // ldmatrix lane-offset maps
    const int arow = (lane & 7) + ((lane >> 3) & 1) * 8;  // A-frag / trans-B
    const int acol = (lane >> 4) * 8;
    const int brow = (lane & 7) + ((lane >> 4) & 1) * 8;  // non-trans B (K)
    const int bcol = ((lane >> 3) & 1) * 8;

    const size_t headOff = (size_t)b * NN * DD + (size_t)h * 128;
    const half* Qp = Q + headOff + (size_t)(qt * 128) * DD;
    const half* Kp = K + headOff;
    const half* Vp = V + headOff;

    auto load_kv = [&](int kt, int bufi) {
#pragma unroll
        for (int j = 0; j < 4; j++) {
            int ch = tid + 256 * j;          // 1024 chunks of 8 halves each
            int r = ch >> 4, c = (ch & 15) * 8;
            const size_t go = (size_t)(kt * 64 + r) * DD + c;
            cp16(&Ks[bufi * KVSZ + r * QP + c], Kp + go);
            cp16(&Vs[bufi * KVSZ + r * QP + c], Vp + go);
        }
    };

    // Q tile: 2048 chunks of 8 halves
#pragma unroll
    for (int j = 0; j < 8; j++) {
        int ch = tid + 256 * j;
        int r = ch >> 4, c = (ch & 15) * 8;
        cp16(&Qs[r * QP + c], Qp + (size_t)r * DD + c);
    }
    load_kv(0, 0);
    asm volatile("cp.async.commit_group;" ::: "memory");

    float o[16][4] = {};   // 16 rows x 128 d-cols per warp
    float m_lo = -1e30f, m_hi = -1e30f, l_lo = 0.f, l_hi = 0.f;

    for (int kt = 0; kt < 32; kt++) {
        asm volatile("cp.async.wait_group 0;" ::: "memory");
        __syncthreads();  // tile kt visible; prev-iter reads of this buf done
        if (kt + 1 < 32) {
            load_kv(kt + 1, (kt + 1) & 1);
            asm volatile("cp.async.commit_group;" ::: "memory");
        }
        const half* Kb = Ks + (kt & 1) * KVSZ;
        const half* Vb = Vs + (kt & 1) * KVSZ;

        // --- S = Q K^T : warp tile 16 x 64, k = 128 ---
        float s[8][4] = {};
#pragma unroll
        for (int ks = 0; ks < 8; ks++) {
            uint32_t a[4];
            ldsm4(a[0], a[1], a[2], a[3],
                  Qs + (wid * 16 + arow) * QP + ks * 16 + acol);
#pragma unroll
            for (int ntp = 0; ntp < 4; ntp++) {
                uint32_t bf0[2], bf1[2];
                ldsm4(bf0[0], bf0[1], bf1[0], bf1[1],
                      Kb + (ntp * 16 + brow) * QP + ks * 16 + bcol);
                mma_f16(s[2 * ntp], a, bf0);
                mma_f16(s[2 * ntp + 1], a, bf1);
            }
        }

        // --- warp-local softmax over full 64 kv cols ---
        float pm_lo = -1e30f, pm_hi = -1e30f;
#pragma unroll
        for (int nt = 0; nt < 8; nt++) {
            pm_lo = fmaxf(pm_lo, fmaxf(s[nt][0], s[nt][1]));
            pm_hi = fmaxf(pm_hi, fmaxf(s[nt][2], s[nt][3]));
        }
        pm_lo = fmaxf(pm_lo, __shfl_xor_sync(0xffffffffu, pm_lo, 1));
        pm_lo = fmaxf(pm_lo, __shfl_xor_sync(0xffffffffu, pm_lo, 2));
        pm_hi = fmaxf(pm_hi, __shfl_xor_sync(0xffffffffu, pm_hi, 1));
        pm_hi = fmaxf(pm_hi, __shfl_xor_sync(0xffffffffu, pm_hi, 2));
        float mnew_lo = fmaxf(m_lo, pm_lo);
        float mnew_hi = fmaxf(m_hi, pm_hi);
        float al_lo = __expf(m_lo - mnew_lo);
        float al_hi = __expf(m_hi - mnew_hi);
        m_lo = mnew_lo;
        m_hi = mnew_hi;

        // exp -> P directly as PV A-fragments (C-frag layout == A-frag layout)
        uint32_t aP[4][4];
        float sum_lo = 0.f, sum_hi = 0.f;
#pragma unroll
        for (int nt = 0; nt < 8; nt++) {
            float p0 = __expf(s[nt][0] - mnew_lo);
            float p1 = __expf(s[nt][1] - mnew_lo);
            float p2 = __expf(s[nt][2] - mnew_hi);
            float p3 = __expf(s[nt][3] - mnew_hi);
            sum_lo += p0 + p1;
            sum_hi += p2 + p3;
            int kc = nt >> 1;
            if ((nt & 1) == 0) {
                aP[kc][0] = h2u(__floats2half2_rn(p0, p1));
                aP[kc][1] = h2u(__floats2half2_rn(p2, p3));
            } else {
                aP[kc][2] = h2u(__floats2half2_rn(p0, p1));
                aP[kc][3] = h2u(__floats2half2_rn(p2, p3));
            }
        }
        sum_lo += __shfl_xor_sync(0xffffffffu, sum_lo, 1);
        sum_lo += __shfl_xor_sync(0xffffffffu, sum_lo, 2);
        sum_hi += __shfl_xor_sync(0xffffffffu, sum_hi, 1);
        sum_hi += __shfl_xor_sync(0xffffffffu, sum_hi, 2);
        l_lo = l_lo * al_lo + sum_lo;
        l_hi = l_hi * al_hi + sum_hi;

        // rescale O
#pragma unroll
        for (int nt = 0; nt < 16; nt++) {
            o[nt][0] *= al_lo;
            o[nt][1] *= al_lo;
            o[nt][2] *= al_hi;
            o[nt][3] *= al_hi;
        }

        // --- O += P V : warp tile 16 rows x 128 d-cols, k = 64 ---
#pragma unroll
        for (int kc = 0; kc < 4; kc++) {
#pragma unroll
            for (int ntp = 0; ntp < 8; ntp++) {
                uint32_t bf0[2], bf1[2];
                ldsm4t(bf0[0], bf0[1], bf1[0], bf1[1],
                       Vb + (kc * 16 + arow) * QP + ntp * 16 + acol);
                mma_f16(o[2 * ntp], aP[kc], bf0);
                mma_f16(o[2 * ntp + 1], aP[kc], bf1);
            }
        }
    }

    // --- epilogue ---
    float inv_lo = 1.f / l_lo;
    float inv_hi = 1.f / l_hi;
    half* Op = O + headOff + (size_t)(qt * 128) * DD;
#pragma unroll
    for (int nt = 0; nt < 16; nt++) {
        int cc = nt * 8 + 2 * c4;
        *(half2*)(Op + (size_t)q0 * DD + cc) =
            __floats2half2_rn(o[nt][0] * inv_lo, o[nt][1] * inv_lo);
        *(half2*)(Op + (size_t)q1 * DD + cc) =
            __floats2half2_rn(o[nt][2] * inv_hi, o[nt][3] * inv_hi);
    }
}

// ---------------------------------------------------------------------------
extern "C" void kernel_launch(void* const* d_in, const int* in_sizes, int n_in,
                              void* d_out, int out_size)
{
    const float* x  = (const float*)d_in[0];
    const float* Wq = (const float*)d_in[1];
    const float* Wk = (const float*)d_in[2];
    const float* Wv = (const float*)d_in[3];
    const float* Wo = (const float*)d_in[4];
    float* out = (float*)d_out;

    half *xh, *wqh, *wkh, *wvh, *woh, *q, *k, *v, *a;
    cudaGetSymbolAddress((void**)&xh,  g_xh);
    cudaGetSymbolAddress((void**)&wqh, g_wqh);
    cudaGetSymbolAddress((void**)&wkh, g_wkh);
    cudaGetSymbolAddress((void**)&wvh, g_wvh);
    cudaGetSymbolAddress((void**)&woh, g_woh);
    cudaGetSymbolAddress((void**)&q, g_q);
    cudaGetSymbolAddress((void**)&k, g_k);
    cudaGetSymbolAddress((void**)&v, g_v);
    cudaGetSymbolAddress((void**)&a, g_a);

    const float scale = 0.08838834764831845f;  // 1/sqrt(128) folded into Wq

    f2h_kernel<<<2048, 256>>>(x,  xh,  MTOT * DD / 4, 1.0f);
    f2h_kernel<<<512,  256>>>(Wq, wqh, DD * DD / 4, scale);
    f2h_kernel<<<512,  256>>>(Wk, wkh, DD * DD / 4, 1.0f);
    f2h_kernel<<<512,  256>>>(Wv, wvh, DD * DD / 4, 1.0f);
    f2h_kernel<<<512,  256>>>(Wo, woh, DD * DD / 4, 1.0f);

    const int gemm_smem = (2 * 128 * GAH + 2 * 32 * GBH) * 2;  // 37888
    cudaFuncSetAttribute(gemm_f16<true>,
                         cudaFuncAttributeMaxDynamicSharedMemorySize, gemm_smem);
    cudaFuncSetAttribute(gemm_f16<false>,
                         cudaFuncAttributeMaxDynamicSharedMemorySize, gemm_smem);
    const int attn_smem = (128 * QP + 4 * KVSZ) * 2;  // 104448
    cudaFuncSetAttribute(attn_f16,
                         cudaFuncAttributeMaxDynamicSharedMemorySize, attn_smem);

    // fused QKV projection (half out)
    gemm_f16<true><<<dim3(DD / 128, MTOT / 128, 3), 256, gemm_smem>>>(
        xh, wqh, wkh, wvh, q, k, v, MTOT, DD, DD);

    attn_f16<<<dim3(NN / 128, BB * 8), 256, attn_smem>>>(q, k, v, a);

    // output projection (float out)
    gemm_f16<false><<<dim3(DD / 128, MTOT / 128, 1), 256, gemm_smem>>>(
        a, woh, woh, woh, out, out, out, MTOT, DD, DD);
}

// round 13
// speedup vs baseline: 21.4389x; 1.0591x over previous
#include <cuda_runtime.h>
#include <cuda_fp16.h>
#include <cstdint>

#define BB 4
#define NN 2048
#define DD 1024
#define MTOT (BB * NN)  // 8192

// fp16 scratch (allocation-free rule: __device__ globals)
static __device__ __align__(256) half g_xh[MTOT * DD];
static __device__ __align__(256) half g_wqh[DD * DD];
static __device__ __align__(256) half g_wkh[DD * DD];
static __device__ __align__(256) half g_wvh[DD * DD];
static __device__ __align__(256) half g_woh[DD * DD];
static __device__ __align__(256) half g_q[MTOT * DD];
static __device__ __align__(256) half g_k[MTOT * DD];
static __device__ __align__(256) half g_v[MTOT * DD];
static __device__ __align__(256) half g_a[MTOT * DD];

// ---------------------------------------------------------------------------
__device__ __forceinline__ uint32_t h2u(half2 h) {
    return *reinterpret_cast<uint32_t*>(&h);
}

__device__ __forceinline__ void mma_f16(float d[4], const uint32_t a[4],
                                        const uint32_t b[2]) {
    asm volatile(
        "mma.sync.aligned.m16n8k16.row.col.f32.f16.f16.f32 "
        "{%0,%1,%2,%3}, {%4,%5,%6,%7}, {%8,%9}, {%0,%1,%2,%3};"
        : "+f"(d[0]), "+f"(d[1]), "+f"(d[2]), "+f"(d[3])
        : "r"(a[0]), "r"(a[1]), "r"(a[2]), "r"(a[3]), "r"(b[0]), "r"(b[1]));
}

__device__ __forceinline__ void ldsm4(uint32_t& m0, uint32_t& m1, uint32_t& m2,
                                      uint32_t& m3, const half* p) {
    uint32_t sa = (uint32_t)__cvta_generic_to_shared(p);
    asm volatile(
        "ldmatrix.sync.aligned.m8n8.x4.shared.b16 {%0,%1,%2,%3}, [%4];"
        : "=r"(m0), "=r"(m1), "=r"(m2), "=r"(m3) : "r"(sa));
}

__device__ __forceinline__ void ldsm4t(uint32_t& m0, uint32_t& m1, uint32_t& m2,
                                       uint32_t& m3, const half* p) {
    uint32_t sa = (uint32_t)__cvta_generic_to_shared(p);
    asm volatile(
        "ldmatrix.sync.aligned.m8n8.x4.trans.shared.b16 {%0,%1,%2,%3}, [%4];"
        : "=r"(m0), "=r"(m1), "=r"(m2), "=r"(m3) : "r"(sa));
}

__device__ __forceinline__ void cp16(void* smem, const void* g) {
    uint32_t s = (uint32_t)__cvta_generic_to_shared(smem);
    asm volatile("cp.async.ca.shared.global [%0], [%1], 16;" :: "r"(s), "l"(g));
}

// ---------------------------------------------------------------------------
// converts
// ---------------------------------------------------------------------------
__global__ void f2h_kernel(const float* __restrict__ in, half* __restrict__ out,
                           int n4, float s)
{
    int i = blockIdx.x * blockDim.x + threadIdx.x;
    int stride = gridDim.x * blockDim.x;
    for (; i < n4; i += stride) {
        float4 f = ((const float4*)in)[i];
        ((half2*)out)[2 * i]     = __floats2half2_rn(f.x * s, f.y * s);
        ((half2*)out)[2 * i + 1] = __floats2half2_rn(f.z * s, f.w * s);
    }
}

// fused 4-weight convert; blockIdx.y selects the weight. Wq gets qscale.
__global__ void w2h_kernel(const float* __restrict__ Wq,
                           const float* __restrict__ Wk,
                           const float* __restrict__ Wv,
                           const float* __restrict__ Wo,
                           half* oq, half* ok, half* ov, half* oo,
                           float qscale)
{
    const int wsel = blockIdx.y;
    const float* in = (wsel == 0) ? Wq : (wsel == 1) ? Wk : (wsel == 2) ? Wv : Wo;
    half* out = (wsel == 0) ? oq : (wsel == 1) ? ok : (wsel == 2) ? ov : oo;
    const float s = (wsel == 0) ? qscale : 1.0f;
    const int n4 = DD * DD / 4;
    int i = blockIdx.x * blockDim.x + threadIdx.x;
    int stride = gridDim.x * blockDim.x;
    for (; i < n4; i += stride) {
        float4 f = ((const float4*)in)[i];
        ((half2*)out)[2 * i]     = __floats2half2_rn(f.x * s, f.y * s);
        ((half2*)out)[2 * i + 1] = __floats2half2_rn(f.z * s, f.w * s);
    }
}

// ---------------------------------------------------------------------------
// fp16 GEMM (unchanged): block 128x128, BK=32, 256 thr, 2-stage cp.async.
// ---------------------------------------------------------------------------
#define GAH 40
#define GBH 136

template <bool HOUT>
__global__ __launch_bounds__(256, 2) void gemm_f16(
    const half* __restrict__ A,
    const half* __restrict__ W0, const half* __restrict__ W1,
    const half* __restrict__ W2,
    void* __restrict__ C0, void* __restrict__ C1, void* __restrict__ C2,
    int M, int N, int K)
{
    const half* Bm = (blockIdx.z == 0) ? W0 : (blockIdx.z == 1) ? W1 : W2;
    void* Cv = (blockIdx.z == 0) ? C0 : (blockIdx.z == 1) ? C1 : C2;

    extern __shared__ half gsm[];
    half* As = gsm;                  // [2][128*GAH]
    half* Bs = gsm + 2 * 128 * GAH;  // [2][32*GBH]

    const int tid = threadIdx.x;
    const int lane = tid & 31;
    const int wid = tid >> 5;
    const int wm = (wid & 1) * 64;
    const int wn = (wid >> 1) * 32;
    const int g  = lane >> 2;
    const int c4 = lane & 3;
    const int rowBase = blockIdx.y * 128;
    const int colBase = blockIdx.x * 128;

    const int arow = (lane & 7) + ((lane >> 3) & 1) * 8;
    const int acol = (lane >> 4) * 8;

    float acc[4][4][4] = {};

    auto load_stage = [&](int kt, int bufi) {
        half* Asb = As + bufi * 128 * GAH;
        half* Bsb = Bs + bufi * 32 * GBH;
#pragma unroll
        for (int j = 0; j < 2; j++) {
            int ch = tid + 256 * j;
            int r = ch >> 2, c = (ch & 3) * 8;
            cp16(&Asb[r * GAH + c], A + (size_t)(rowBase + r) * K + kt + c);
        }
#pragma unroll
        for (int j = 0; j < 2; j++) {
            int ch = tid + 256 * j;
            int kr = ch >> 4, c = (ch & 15) * 8;
            cp16(&Bsb[kr * GBH + c],
                 Bm + (size_t)(kt + kr) * N + colBase + c);
        }
    };

    load_stage(0, 0);
    asm volatile("cp.async.commit_group;" ::: "memory");

    const int T = K / 32;
    for (int t = 0; t < T; t++) {
        if (t + 1 < T) {
            load_stage((t + 1) * 32, (t + 1) & 1);
            asm volatile("cp.async.commit_group;" ::: "memory");
            asm volatile("cp.async.wait_group 1;" ::: "memory");
        } else {
            asm volatile("cp.async.wait_group 0;" ::: "memory");
        }
        __syncthreads();

        const half* Asb = As + (t & 1) * 128 * GAH;
        const half* Bsb = Bs + (t & 1) * 32 * GBH;

#pragma unroll
        for (int ks = 0; ks < 2; ks++) {
            uint32_t a[4][4], b[4][2];
#pragma unroll
            for (int mt = 0; mt < 4; mt++)
                ldsm4(a[mt][0], a[mt][1], a[mt][2], a[mt][3],
                      Asb + (wm + mt * 16 + arow) * GAH + ks * 16 + acol);
#pragma unroll
            for (int ntp = 0; ntp < 2; ntp++)
                ldsm4t(b[2 * ntp][0], b[2 * ntp][1],
                       b[2 * ntp + 1][0], b[2 * ntp + 1][1],
                       Bsb + (ks * 16 + arow) * GBH + wn + ntp * 16 + acol);
#pragma unroll
            for (int mt = 0; mt < 4; mt++)
#pragma unroll
                for (int nt = 0; nt < 4; nt++)
                    mma_f16(acc[mt][nt], a[mt], b[nt]);
        }
        __syncthreads();
    }

#pragma unroll
    for (int mt = 0; mt < 4; mt++) {
        int r0 = rowBase + wm + mt * 16 + g;
#pragma unroll
        for (int nt = 0; nt < 4; nt++) {
            int cc = colBase + wn + nt * 8 + 2 * c4;
            if (HOUT) {
                half* C = (half*)Cv;
                *(half2*)(C + (size_t)r0 * N + cc) =
                    __floats2half2_rn(acc[mt][nt][0], acc[mt][nt][1]);
                *(half2*)(C + (size_t)(r0 + 8) * N + cc) =
                    __floats2half2_rn(acc[mt][nt][2], acc[mt][nt][3]);
            } else {
                float* C = (float*)Cv;
                *(float2*)(C + (size_t)r0 * N + cc) =
                    make_float2(acc[mt][nt][0], acc[mt][nt][1]);
                *(float2*)(C + (size_t)(r0 + 8) * N + cc) =
                    make_float2(acc[mt][nt][2], acc[mt][nt][3]);
            }
        }
    }
}

// ---------------------------------------------------------------------------
// fp16 flash attention, FA2-style, 4 warps x 32 q-rows (128 threads),
// 2 blocks/SM. Block = 128 q-rows of one (b,h). KV tile 64, double-buffered.
// Warp = 32 q-rows (two 16-row MMA blocks) x full width. K/V fragment reads
// amortized over 2x rows vs R12 -> LDS/iter drops 288KB -> 160KB.
// Softmax warp-local; P in registers.
// smem: Qs 128*136 + Ks 2*64*136 + Vs 2*64*136 halves = 104448 B.
// ---------------------------------------------------------------------------
#define QP 136
#define KVSZ (64 * QP)

__global__ __launch_bounds__(128, 2) void attn_f16(
    const half* __restrict__ Q, const half* __restrict__ K,
    const half* __restrict__ V, half* __restrict__ O)
{
    extern __shared__ half smh[];
    half* Qs = smh;                    // 128*136
    half* Ks = Qs + 128 * QP;          // [2][64*136]
    half* Vs = Ks + 2 * KVSZ;          // [2][64*136]

    const int tid = threadIdx.x;
    const int lane = tid & 31;
    const int wid = tid >> 5;          // 0..3 -> q rows 32*wid..
    const int g  = lane >> 2;
    const int c4 = lane & 3;
    const int qt = blockIdx.x;
    const int bh = blockIdx.y;
    const int b = bh >> 3;
    const int h = bh & 7;

    const int rb0 = wid * 32;          // first 16-row block
    const int rb1 = wid * 32 + 16;     // second 16-row block
    const int qa = rb0 + g;            // grp0 rows (regs 0,1)
    const int qb = qa + 8;             // grp0 rows (regs 2,3)
    const int qc = rb1 + g;            // grp1 rows (regs 0,1)
    const int qd = qc + 8;             // grp1 rows (regs 2,3)

    // ldmatrix lane-offset maps
    const int arow = (lane & 7) + ((lane >> 3) & 1) * 8;  // A-frag / trans-B
    const int acol = (lane >> 4) * 8;
    const int brow = (lane & 7) + ((lane >> 4) & 1) * 8;  // non-trans B (K)
    const int bcol = ((lane >> 3) & 1) * 8;

    const size_t headOff = (size_t)b * NN * DD + (size_t)h * 128;
    const half* Qp = Q + headOff + (size_t)(qt * 128) * DD;
    const half* Kp = K + headOff;
    const half* Vp = V + headOff;

    auto load_kv = [&](int kt, int bufi) {
#pragma unroll
        for (int j = 0; j < 8; j++) {
            int ch = tid + 128 * j;          // 1024 chunks of 8 halves each
            int r = ch >> 4, c = (ch & 15) * 8;
            const size_t go = (size_t)(kt * 64 + r) * DD + c;
            cp16(&Ks[bufi * KVSZ + r * QP + c], Kp + go);
            cp16(&Vs[bufi * KVSZ + r * QP + c], Vp + go);
        }
    };

    // Q tile: 2048 chunks of 8 halves
#pragma unroll
    for (int j = 0; j < 16; j++) {
        int ch = tid + 128 * j;
        int r = ch >> 4, c = (ch & 15) * 8;
        cp16(&Qs[r * QP + c], Qp + (size_t)r * DD + c);
    }
    load_kv(0, 0);
    asm volatile("cp.async.commit_group;" ::: "memory");

    float o[2][16][4] = {};   // [row-block][d-tile][frag]
    float m_a = -1e30f, m_b = -1e30f, m_c = -1e30f, m_d = -1e30f;
    float l_a = 0.f, l_b = 0.f, l_c = 0.f, l_d = 0.f;

    for (int kt = 0; kt < 32; kt++) {
        asm volatile("cp.async.wait_group 0;" ::: "memory");
        __syncthreads();  // tile kt visible; prev-iter reads of this buf done
        if (kt + 1 < 32) {
            load_kv(kt + 1, (kt + 1) & 1);
            asm volatile("cp.async.commit_group;" ::: "memory");
        }
        const half* Kb = Ks + (kt & 1) * KVSZ;
        const half* Vb = Vs + (kt & 1) * KVSZ;

        // --- S = Q K^T : warp tile 32 x 64, k = 128 ---
        float s[2][8][4] = {};
#pragma unroll
        for (int ks = 0; ks < 8; ks++) {
            uint32_t a0[4], a1[4];
            ldsm4(a0[0], a0[1], a0[2], a0[3],
                  Qs + (rb0 + arow) * QP + ks * 16 + acol);
            ldsm4(a1[0], a1[1], a1[2], a1[3],
                  Qs + (rb1 + arow) * QP + ks * 16 + acol);
#pragma unroll
            for (int ntp = 0; ntp < 4; ntp++) {
                uint32_t bf0[2], bf1[2];
                ldsm4(bf0[0], bf0[1], bf1[0], bf1[1],
                      Kb + (ntp * 16 + brow) * QP + ks * 16 + bcol);
                mma_f16(s[0][2 * ntp], a0, bf0);
                mma_f16(s[0][2 * ntp + 1], a0, bf1);
                mma_f16(s[1][2 * ntp], a1, bf0);
                mma_f16(s[1][2 * ntp + 1], a1, bf1);
            }
        }

        // --- warp-local softmax (4 row sets per thread) ---
        float pa = -1e30f, pb = -1e30f, pc = -1e30f, pd = -1e30f;
#pragma unroll
        for (int nt = 0; nt < 8; nt++) {
            pa = fmaxf(pa, fmaxf(s[0][nt][0], s[0][nt][1]));
            pb = fmaxf(pb, fmaxf(s[0][nt][2], s[0][nt][3]));
            pc = fmaxf(pc, fmaxf(s[1][nt][0], s[1][nt][1]));
            pd = fmaxf(pd, fmaxf(s[1][nt][2], s[1][nt][3]));
        }
        pa = fmaxf(pa, __shfl_xor_sync(0xffffffffu, pa, 1));
        pa = fmaxf(pa, __shfl_xor_sync(0xffffffffu, pa, 2));
        pb = fmaxf(pb, __shfl_xor_sync(0xffffffffu, pb, 1));
        pb = fmaxf(pb, __shfl_xor_sync(0xffffffffu, pb, 2));
        pc = fmaxf(pc, __shfl_xor_sync(0xffffffffu, pc, 1));
        pc = fmaxf(pc, __shfl_xor_sync(0xffffffffu, pc, 2));
        pd = fmaxf(pd, __shfl_xor_sync(0xffffffffu, pd, 1));
        pd = fmaxf(pd, __shfl_xor_sync(0xffffffffu, pd, 2));
        float na = fmaxf(m_a, pa), nb = fmaxf(m_b, pb);
        float nc = fmaxf(m_c, pc), nd = fmaxf(m_d, pd);
        float aa = __expf(m_a - na), ab = __expf(m_b - nb);
        float ac = __expf(m_c - nc), ad = __expf(m_d - nd);
        m_a = na; m_b = nb; m_c = nc; m_d = nd;

        // exp -> P as PV A-fragments (C-frag layout == A-frag layout)
        uint32_t aP[2][4][4];
        float sa = 0.f, sb = 0.f, sc = 0.f, sd = 0.f;
#pragma unroll
        for (int nt = 0; nt < 8; nt++) {
            int kc = nt >> 1;
            int sl = (nt & 1) * 2;  // 0 or 2
            {
                float p0 = __expf(s[0][nt][0] - na);
                float p1 = __expf(s[0][nt][1] - na);
                float p2 = __expf(s[0][nt][2] - nb);
                float p3 = __expf(s[0][nt][3] - nb);
                sa += p0 + p1;
                sb += p2 + p3;
                aP[0][kc][sl]     = h2u(__floats2half2_rn(p0, p1));
                aP[0][kc][sl + 1] = h2u(__floats2half2_rn(p2, p3));
            }
            {
                float p0 = __expf(s[1][nt][0] - nc);
                float p1 = __expf(s[1][nt][1] - nc);
                float p2 = __expf(s[1][nt][2] - nd);
                float p3 = __expf(s[1][nt][3] - nd);
                sc += p0 + p1;
                sd += p2 + p3;
                aP[1][kc][sl]     = h2u(__floats2half2_rn(p0, p1));
                aP[1][kc][sl + 1] = h2u(__floats2half2_rn(p2, p3));
            }
        }
        sa += __shfl_xor_sync(0xffffffffu, sa, 1);
        sa += __shfl_xor_sync(0xffffffffu, sa, 2);
        sb += __shfl_xor_sync(0xffffffffu, sb, 1);
        sb += __shfl_xor_sync(0xffffffffu, sb, 2);
        sc += __shfl_xor_sync(0xffffffffu, sc, 1);
        sc += __shfl_xor_sync(0xffffffffu, sc, 2);
        sd += __shfl_xor_sync(0xffffffffu, sd, 1);
        sd += __shfl_xor_sync(0xffffffffu, sd, 2);
        l_a = l_a * aa + sa;
        l_b = l_b * ab + sb;
        l_c = l_c * ac + sc;
        l_d = l_d * ad + sd;

        // rescale O
#pragma unroll
        for (int nt = 0; nt < 16; nt++) {
            o[0][nt][0] *= aa; o[0][nt][1] *= aa;
            o[0][nt][2] *= ab; o[0][nt][3] *= ab;
            o[1][nt][0] *= ac; o[1][nt][1] *= ac;
            o[1][nt][2] *= ad; o[1][nt][3] *= ad;
        }

        // --- O += P V : warp tile 32 rows x 128 d-cols, k = 64 ---
#pragma unroll
        for (int kc = 0; kc < 4; kc++) {
#pragma unroll
            for (int ntp = 0; ntp < 8; ntp++) {
                uint32_t bf0[2], bf1[2];
                ldsm4t(bf0[0], bf0[1], bf1[0], bf1[1],
                       Vb + (kc * 16 + arow) * QP + ntp * 16 + acol);
                mma_f16(o[0][2 * ntp], aP[0][kc], bf0);
                mma_f16(o[0][2 * ntp + 1], aP[0][kc], bf1);
                mma_f16(o[1][2 * ntp], aP[1][kc], bf0);
                mma_f16(o[1][2 * ntp + 1], aP[1][kc], bf1);
            }
        }
    }

    // --- epilogue ---
    float ia = 1.f / l_a, ib = 1.f / l_b, ic = 1.f / l_c, id = 1.f / l_d;
    half* Op = O + headOff + (size_t)(qt * 128) * DD;
#pragma unroll
    for (int nt = 0; nt < 16; nt++) {
        int cc = nt * 8 + 2 * c4;
        *(half2*)(Op + (size_t)qa * DD + cc) =
            __floats2half2_rn(o[0][nt][0] * ia, o[0][nt][1] * ia);
        *(half2*)(Op + (size_t)qb * DD + cc) =
            __floats2half2_rn(o[0][nt][2] * ib, o[0][nt][3] * ib);
        *(half2*)(Op + (size_t)qc * DD + cc) =
            __floats2half2_rn(o[1][nt][0] * ic, o[1][nt][1] * ic);
        *(half2*)(Op + (size_t)qd * DD + cc) =
            __floats2half2_rn(o[1][nt][2] * id, o[1][nt][3] * id);
    }
}

// ---------------------------------------------------------------------------
extern "C" void kernel_launch(void* const* d_in, const int* in_sizes, int n_in,
                              void* d_out, int out_size)
{
    const float* x  = (const float*)d_in[0];
    const float* Wq = (const float*)d_in[1];
    const float* Wk = (const float*)d_in[2];
    const float* Wv = (const float*)d_in[3];
    const float* Wo = (const float*)d_in[4];
    float* out = (float*)d_out;

    half *xh, *wqh, *wkh, *wvh, *woh, *q, *k, *v, *a;
    cudaGetSymbolAddress((void**)&xh,  g_xh);
    cudaGetSymbolAddress((void**)&wqh, g_wqh);
    cudaGetSymbolAddress((void**)&wkh, g_wkh);
    cudaGetSymbolAddress((void**)&wvh, g_wvh);
    cudaGetSymbolAddress((void**)&woh, g_woh);
    cudaGetSymbolAddress((void**)&q, g_q);
    cudaGetSymbolAddress((void**)&k, g_k);
    cudaGetSymbolAddress((void**)&v, g_v);
    cudaGetSymbolAddress((void**)&a, g_a);

    const float scale = 0.08838834764831845f;  // 1/sqrt(128) folded into Wq

    f2h_kernel<<<2048, 256>>>(x, xh, MTOT * DD / 4, 1.0f);
    w2h_kernel<<<dim3(256, 4), 256>>>(Wq, Wk, Wv, Wo, wqh, wkh, wvh, woh, scale);

    const int gemm_smem = (2 * 128 * GAH + 2 * 32 * GBH) * 2;  // 37888
    cudaFuncSetAttribute(gemm_f16<true>,
                         cudaFuncAttributeMaxDynamicSharedMemorySize, gemm_smem);
    cudaFuncSetAttribute(gemm_f16<false>,
                         cudaFuncAttributeMaxDynamicSharedMemorySize, gemm_smem);
    const int attn_smem = (128 * QP + 4 * KVSZ) * 2;  // 104448
    cudaFuncSetAttribute(attn_f16,
                         cudaFuncAttributeMaxDynamicSharedMemorySize, attn_smem);

    // fused QKV projection (half out)
    gemm_f16<true><<<dim3(DD / 128, MTOT / 128, 3), 256, gemm_smem>>>(
        xh, wqh, wkh, wvh, q, k, v, MTOT, DD, DD);

    attn_f16<<<dim3(NN / 128, BB * 8), 128, attn_smem>>>(q, k, v, a);

    // output projection (float out)
    gemm_f16<false><<<dim3(DD / 128, MTOT / 128, 1), 256, gemm_smem>>>(
        a, woh, woh, woh, out, out, out, MTOT, DD, DD);
}

// round 14
// speedup vs baseline: 23.7946x; 1.1099x over previous
#include <cuda_runtime.h>
#include <cuda_fp16.h>
#include <cstdint>

#define BB 4
#define NN 2048
#define DD 1024
#define MTOT (BB * NN)  // 8192

// fp16 scratch (allocation-free rule: __device__ globals)
static __device__ __align__(256) half g_xh[MTOT * DD];
static __device__ __align__(256) half g_wqh[DD * DD];
static __device__ __align__(256) half g_wkh[DD * DD];
static __device__ __align__(256) half g_wvh[DD * DD];
static __device__ __align__(256) half g_woh[DD * DD];
static __device__ __align__(256) half g_q[MTOT * DD];
static __device__ __align__(256) half g_k[MTOT * DD];
static __device__ __align__(256) half g_v[MTOT * DD];
static __device__ __align__(256) half g_a[MTOT * DD];

// ---------------------------------------------------------------------------
__device__ __forceinline__ uint32_t h2u(half2 h) {
    return *reinterpret_cast<uint32_t*>(&h);
}

__device__ __forceinline__ float ex2(float x) {
    float r;
    asm("ex2.approx.f32 %0, %1;" : "=f"(r) : "f"(x));
    return r;
}

__device__ __forceinline__ void mma_f16(float d[4], const uint32_t a[4],
                                        const uint32_t b[2]) {
    asm volatile(
        "mma.sync.aligned.m16n8k16.row.col.f32.f16.f16.f32 "
        "{%0,%1,%2,%3}, {%4,%5,%6,%7}, {%8,%9}, {%0,%1,%2,%3};"
        : "+f"(d[0]), "+f"(d[1]), "+f"(d[2]), "+f"(d[3])
        : "r"(a[0]), "r"(a[1]), "r"(a[2]), "r"(a[3]), "r"(b[0]), "r"(b[1]));
}

__device__ __forceinline__ void ldsm4(uint32_t& m0, uint32_t& m1, uint32_t& m2,
                                      uint32_t& m3, const half* p) {
    uint32_t sa = (uint32_t)__cvta_generic_to_shared(p);
    asm volatile(
        "ldmatrix.sync.aligned.m8n8.x4.shared.b16 {%0,%1,%2,%3}, [%4];"
        : "=r"(m0), "=r"(m1), "=r"(m2), "=r"(m3) : "r"(sa));
}

__device__ __forceinline__ void ldsm4t(uint32_t& m0, uint32_t& m1, uint32_t& m2,
                                       uint32_t& m3, const half* p) {
    uint32_t sa = (uint32_t)__cvta_generic_to_shared(p);
    asm volatile(
        "ldmatrix.sync.aligned.m8n8.x4.trans.shared.b16 {%0,%1,%2,%3}, [%4];"
        : "=r"(m0), "=r"(m1), "=r"(m2), "=r"(m3) : "r"(sa));
}

__device__ __forceinline__ void cp16(void* smem, const void* g) {
    uint32_t s = (uint32_t)__cvta_generic_to_shared(smem);
    asm volatile("cp.async.ca.shared.global [%0], [%1], 16;" :: "r"(s), "l"(g));
}

// ---------------------------------------------------------------------------
// fused convert: y=0 -> x (scale 1), y=1..4 -> Wq(qscale)/Wk/Wv/Wo
// ---------------------------------------------------------------------------
__global__ void conv_all(const float* __restrict__ x,
                         const float* __restrict__ Wq,
                         const float* __restrict__ Wk,
                         const float* __restrict__ Wv,
                         const float* __restrict__ Wo,
                         half* ox, half* oq, half* ok, half* ov, half* oo,
                         float qscale)
{
    const int ysel = blockIdx.y;
    const float* in = (ysel == 0) ? x : (ysel == 1) ? Wq : (ysel == 2) ? Wk
                                      : (ysel == 3) ? Wv : Wo;
    half* out = (ysel == 0) ? ox : (ysel == 1) ? oq : (ysel == 2) ? ok
                                 : (ysel == 3) ? ov : oo;
    const float s = (ysel == 1) ? qscale : 1.0f;
    const int n4 = (ysel == 0) ? (MTOT * DD / 4) : (DD * DD / 4);
    int i = blockIdx.x * blockDim.x + threadIdx.x;
    int stride = gridDim.x * blockDim.x;
    for (; i < n4; i += stride) {
        float4 f = ((const float4*)in)[i];
        ((half2*)out)[2 * i]     = __floats2half2_rn(f.x * s, f.y * s);
        ((half2*)out)[2 * i + 1] = __floats2half2_rn(f.z * s, f.w * s);
    }
}

// ---------------------------------------------------------------------------
// fp16 GEMM v2: block 128x128, BK=32, 128 threads (4 warps, 2m x 2n),
// warp tile 64x64, 3-stage cp.async (ONE barrier per k-chunk).
// smem: 3*(128*40 + 32*136)*2 = 56832 B -> 2 blocks/SM.
// ---------------------------------------------------------------------------
#define GAH 40
#define GBH 136
#define GSTG (128 * GAH + 32 * GBH)   // halves per stage

template <bool HOUT>
__global__ __launch_bounds__(128, 2) void gemm_f16(
    const half* __restrict__ A,
    const half* __restrict__ W0, const half* __restrict__ W1,
    const half* __restrict__ W2,
    void* __restrict__ C0, void* __restrict__ C1, void* __restrict__ C2,
    int M, int N, int K)
{
    const half* Bm = (blockIdx.z == 0) ? W0 : (blockIdx.z == 1) ? W1 : W2;
    void* Cv = (blockIdx.z == 0) ? C0 : (blockIdx.z == 1) ? C1 : C2;

    extern __shared__ half gsm[];

    const int tid = threadIdx.x;
    const int lane = tid & 31;
    const int wid = tid >> 5;          // 0..3
    const int wm = (wid & 1) * 64;
    const int wn = (wid >> 1) * 64;
    const int g  = lane >> 2;
    const int c4 = lane & 3;
    const int rowBase = blockIdx.y * 128;
    const int colBase = blockIdx.x * 128;

    const int arow = (lane & 7) + ((lane >> 3) & 1) * 8;
    const int acol = (lane >> 4) * 8;

    float acc[4][8][4] = {};

    auto load_stage = [&](int kt, int stg) {
        half* Asb = gsm + stg * GSTG;
        half* Bsb = Asb + 128 * GAH;
#pragma unroll
        for (int j = 0; j < 4; j++) {
            int ch = tid + 128 * j;        // 512 chunks of 8 halves (A)
            int r = ch >> 2, c = (ch & 3) * 8;
            cp16(&Asb[r * GAH + c], A + (size_t)(rowBase + r) * K + kt + c);
        }
#pragma unroll
        for (int j = 0; j < 4; j++) {
            int ch = tid + 128 * j;        // 512 chunks of 8 halves (B)
            int kr = ch >> 4, c = (ch & 15) * 8;
            cp16(&Bsb[kr * GBH + c],
                 Bm + (size_t)(kt + kr) * N + colBase + c);
        }
        asm volatile("cp.async.commit_group;" ::: "memory");
    };

    load_stage(0, 0);
    load_stage(32, 1);

    const int T = K / 32;
    for (int t = 0; t < T; t++) {
        if (t + 1 < T)
            asm volatile("cp.async.wait_group 1;" ::: "memory");
        else
            asm volatile("cp.async.wait_group 0;" ::: "memory");
        __syncthreads();   // stage t ready; all warps done with stage (t-1)

        int stg = t % 3;
        const half* Asb = gsm + stg * GSTG;
        const half* Bsb = Asb + 128 * GAH;

#pragma unroll
        for (int ks = 0; ks < 2; ks++) {
            uint32_t a[4][4], b[8][2];
#pragma unroll
            for (int mt = 0; mt < 4; mt++)
                ldsm4(a[mt][0], a[mt][1], a[mt][2], a[mt][3],
                      Asb + (wm + mt * 16 + arow) * GAH + ks * 16 + acol);
#pragma unroll
            for (int ntp = 0; ntp < 4; ntp++)
                ldsm4t(b[2 * ntp][0], b[2 * ntp][1],
                       b[2 * ntp + 1][0], b[2 * ntp + 1][1],
                       Bsb + (ks * 16 + arow) * GBH + wn + ntp * 16 + acol);
#pragma unroll
            for (int mt = 0; mt < 4; mt++)
#pragma unroll
                for (int nt = 0; nt < 8; nt++)
                    mma_f16(acc[mt][nt], a[mt], b[nt]);
        }

        if (t + 2 < T)
            load_stage((t + 2) * 32, (t + 2) % 3);
    }

#pragma unroll
    for (int mt = 0; mt < 4; mt++) {
        int r0 = rowBase + wm + mt * 16 + g;
#pragma unroll
        for (int nt = 0; nt < 8; nt++) {
            int cc = colBase + wn + nt * 8 + 2 * c4;
            if (HOUT) {
                half* C = (half*)Cv;
                *(half2*)(C + (size_t)r0 * N + cc) =
                    __floats2half2_rn(acc[mt][nt][0], acc[mt][nt][1]);
                *(half2*)(C + (size_t)(r0 + 8) * N + cc) =
                    __floats2half2_rn(acc[mt][nt][2], acc[mt][nt][3]);
            } else {
                float* C = (float*)Cv;
                *(float2*)(C + (size_t)r0 * N + cc) =
                    make_float2(acc[mt][nt][0], acc[mt][nt][1]);
                *(float2*)(C + (size_t)(r0 + 8) * N + cc) =
                    make_float2(acc[mt][nt][2], acc[mt][nt][3]);
            }
        }
    }
}

// ---------------------------------------------------------------------------
// fp16 flash attention (R13 structure + exp2 trick). 128 threads, 4 warps x
// 32 q-rows, 2 blocks/SM. Q pre-scaled by (1/sqrt(128))*log2(e) -> softmax
// runs in base-2 domain, ex2.approx only (no mul).
// ---------------------------------------------------------------------------
#define QP 136
#define KVSZ (64 * QP)

__global__ __launch_bounds__(128, 2) void attn_f16(
    const half* __restrict__ Q, const half* __restrict__ K,
    const half* __restrict__ V, half* __restrict__ O)
{
    extern __shared__ half smh[];
    half* Qs = smh;                    // 128*136
    half* Ks = Qs + 128 * QP;          // [2][64*136]
    half* Vs = Ks + 2 * KVSZ;          // [2][64*136]

    const int tid = threadIdx.x;
    const int lane = tid & 31;
    const int wid = tid >> 5;          // 0..3 -> q rows 32*wid..
    const int g  = lane >> 2;
    const int c4 = lane & 3;
    const int qt = blockIdx.x;
    const int bh = blockIdx.y;
    const int b = bh >> 3;
    const int h = bh & 7;

    const int rb0 = wid * 32;
    const int rb1 = wid * 32 + 16;
    const int qa = rb0 + g;
    const int qb = qa + 8;
    const int qc = rb1 + g;
    const int qd = qc + 8;

    const int arow = (lane & 7) + ((lane >> 3) & 1) * 8;
    const int acol = (lane >> 4) * 8;
    const int brow = (lane & 7) + ((lane >> 4) & 1) * 8;
    const int bcol = ((lane >> 3) & 1) * 8;

    const size_t headOff = (size_t)b * NN * DD + (size_t)h * 128;
    const half* Qp = Q + headOff + (size_t)(qt * 128) * DD;
    const half* Kp = K + headOff;
    const half* Vp = V + headOff;

    auto load_kv = [&](int kt, int bufi) {
#pragma unroll
        for (int j = 0; j < 8; j++) {
            int ch = tid + 128 * j;
            int r = ch >> 4, c = (ch & 15) * 8;
            const size_t go = (size_t)(kt * 64 + r) * DD + c;
            cp16(&Ks[bufi * KVSZ + r * QP + c], Kp + go);
            cp16(&Vs[bufi * KVSZ + r * QP + c], Vp + go);
        }
    };

#pragma unroll
    for (int j = 0; j < 16; j++) {
        int ch = tid + 128 * j;
        int r = ch >> 4, c = (ch & 15) * 8;
        cp16(&Qs[r * QP + c], Qp + (size_t)r * DD + c);
    }
    load_kv(0, 0);
    asm volatile("cp.async.commit_group;" ::: "memory");

    float o[2][16][4] = {};
    float m_a = -1e30f, m_b = -1e30f, m_c = -1e30f, m_d = -1e30f;
    float l_a = 0.f, l_b = 0.f, l_c = 0.f, l_d = 0.f;

    for (int kt = 0; kt < 32; kt++) {
        asm volatile("cp.async.wait_group 0;" ::: "memory");
        __syncthreads();
        if (kt + 1 < 32) {
            load_kv(kt + 1, (kt + 1) & 1);
            asm volatile("cp.async.commit_group;" ::: "memory");
        }
        const half* Kb = Ks + (kt & 1) * KVSZ;
        const half* Vb = Vs + (kt & 1) * KVSZ;

        // --- S = Q K^T (base-2 logits) ---
        float s[2][8][4] = {};
#pragma unroll
        for (int ks = 0; ks < 8; ks++) {
            uint32_t a0[4], a1[4];
            ldsm4(a0[0], a0[1], a0[2], a0[3],
                  Qs + (rb0 + arow) * QP + ks * 16 + acol);
            ldsm4(a1[0], a1[1], a1[2], a1[3],
                  Qs + (rb1 + arow) * QP + ks * 16 + acol);
#pragma unroll
            for (int ntp = 0; ntp < 4; ntp++) {
                uint32_t bf0[2], bf1[2];
                ldsm4(bf0[0], bf0[1], bf1[0], bf1[1],
                      Kb + (ntp * 16 + brow) * QP + ks * 16 + bcol);
                mma_f16(s[0][2 * ntp], a0, bf0);
                mma_f16(s[0][2 * ntp + 1], a0, bf1);
                mma_f16(s[1][2 * ntp], a1, bf0);
                mma_f16(s[1][2 * ntp + 1], a1, bf1);
            }
        }

        // --- warp-local softmax (base 2) ---
        float pa = -1e30f, pb = -1e30f, pc = -1e30f, pd = -1e30f;
#pragma unroll
        for (int nt = 0; nt < 8; nt++) {
            pa = fmaxf(pa, fmaxf(s[0][nt][0], s[0][nt][1]));
            pb = fmaxf(pb, fmaxf(s[0][nt][2], s[0][nt][3]));
            pc = fmaxf(pc, fmaxf(s[1][nt][0], s[1][nt][1]));
            pd = fmaxf(pd, fmaxf(s[1][nt][2], s[1][nt][3]));
        }
        pa = fmaxf(pa, __shfl_xor_sync(0xffffffffu, pa, 1));
        pa = fmaxf(pa, __shfl_xor_sync(0xffffffffu, pa, 2));
        pb = fmaxf(pb, __shfl_xor_sync(0xffffffffu, pb, 1));
        pb = fmaxf(pb, __shfl_xor_sync(0xffffffffu, pb, 2));
        pc = fmaxf(pc, __shfl_xor_sync(0xffffffffu, pc, 1));
        pc = fmaxf(pc, __shfl_xor_sync(0xffffffffu, pc, 2));
        pd = fmaxf(pd, __shfl_xor_sync(0xffffffffu, pd, 1));
        pd = fmaxf(pd, __shfl_xor_sync(0xffffffffu, pd, 2));
        float na = fmaxf(m_a, pa), nb = fmaxf(m_b, pb);
        float nc = fmaxf(m_c, pc), nd = fmaxf(m_d, pd);
        float aa = ex2(m_a - na), ab = ex2(m_b - nb);
        float ac = ex2(m_c - nc), ad = ex2(m_d - nd);
        m_a = na; m_b = nb; m_c = nc; m_d = nd;

        uint32_t aP[2][4][4];
        float sa = 0.f, sb = 0.f, sc = 0.f, sd = 0.f;
#pragma unroll
        for (int nt = 0; nt < 8; nt++) {
            int kc = nt >> 1;
            int sl = (nt & 1) * 2;
            {
                float p0 = ex2(s[0][nt][0] - na);
                float p1 = ex2(s[0][nt][1] - na);
                float p2 = ex2(s[0][nt][2] - nb);
                float p3 = ex2(s[0][nt][3] - nb);
                sa += p0 + p1;
                sb += p2 + p3;
                aP[0][kc][sl]     = h2u(__floats2half2_rn(p0, p1));
                aP[0][kc][sl + 1] = h2u(__floats2half2_rn(p2, p3));
            }
            {
                float p0 = ex2(s[1][nt][0] - nc);
                float p1 = ex2(s[1][nt][1] - nc);
                float p2 = ex2(s[1][nt][2] - nd);
                float p3 = ex2(s[1][nt][3] - nd);
                sc += p0 + p1;
                sd += p2 + p3;
                aP[1][kc][sl]     = h2u(__floats2half2_rn(p0, p1));
                aP[1][kc][sl + 1] = h2u(__floats2half2_rn(p2, p3));
            }
        }
        sa += __shfl_xor_sync(0xffffffffu, sa, 1);
        sa += __shfl_xor_sync(0xffffffffu, sa, 2);
        sb += __shfl_xor_sync(0xffffffffu, sb, 1);
        sb += __shfl_xor_sync(0xffffffffu, sb, 2);
        sc += __shfl_xor_sync(0xffffffffu, sc, 1);
        sc += __shfl_xor_sync(0xffffffffu, sc, 2);
        sd += __shfl_xor_sync(0xffffffffu, sd, 1);
        sd += __shfl_xor_sync(0xffffffffu, sd, 2);
        l_a = l_a * aa + sa;
        l_b = l_b * ab + sb;
        l_c = l_c * ac + sc;
        l_d = l_d * ad + sd;

#pragma unroll
        for (int nt = 0; nt < 16; nt++) {
            o[0][nt][0] *= aa; o[0][nt][1] *= aa;
            o[0][nt][2] *= ab; o[0][nt][3] *= ab;
            o[1][nt][0] *= ac; o[1][nt][1] *= ac;
            o[1][nt][2] *= ad; o[1][nt][3] *= ad;
        }

        // --- O += P V ---
#pragma unroll
        for (int kc = 0; kc < 4; kc++) {
#pragma unroll
            for (int ntp = 0; ntp < 8; ntp++) {
                uint32_t bf0[2], bf1[2];
                ldsm4t(bf0[0], bf0[1], bf1[0], bf1[1],
                       Vb + (kc * 16 + arow) * QP + ntp * 16 + acol);
                mma_f16(o[0][2 * ntp], aP[0][kc], bf0);
                mma_f16(o[0][2 * ntp + 1], aP[0][kc], bf1);
                mma_f16(o[1][2 * ntp], aP[1][kc], bf0);
                mma_f16(o[1][2 * ntp + 1], aP[1][kc], bf1);
            }
        }
    }

    // --- epilogue ---
    float ia = 1.f / l_a, ib = 1.f / l_b, ic = 1.f / l_c, id = 1.f / l_d;
    half* Op = O + headOff + (size_t)(qt * 128) * DD;
#pragma unroll
    for (int nt = 0; nt < 16; nt++) {
        int cc = nt * 8 + 2 * c4;
        *(half2*)(Op + (size_t)qa * DD + cc) =
            __floats2half2_rn(o[0][nt][0] * ia, o[0][nt][1] * ia);
        *(half2*)(Op + (size_t)qb * DD + cc) =
            __floats2half2_rn(o[0][nt][2] * ib, o[0][nt][3] * ib);
        *(half2*)(Op + (size_t)qc * DD + cc) =
            __floats2half2_rn(o[1][nt][0] * ic, o[1][nt][1] * ic);
        *(half2*)(Op + (size_t)qd * DD + cc) =
            __floats2half2_rn(o[1][nt][2] * id, o[1][nt][3] * id);
    }
}

// ---------------------------------------------------------------------------
extern "C" void kernel_launch(void* const* d_in, const int* in_sizes, int n_in,
                              void* d_out, int out_size)
{
    const float* x  = (const float*)d_in[0];
    const float* Wq = (const float*)d_in[1];
    const float* Wk = (const float*)d_in[2];
    const float* Wv = (const float*)d_in[3];
    const float* Wo = (const float*)d_in[4];
    float* out = (float*)d_out;

    half *xh, *wqh, *wkh, *wvh, *woh, *q, *k, *v, *a;
    cudaGetSymbolAddress((void**)&xh,  g_xh);
    cudaGetSymbolAddress((void**)&wqh, g_wqh);
    cudaGetSymbolAddress((void**)&wkh, g_wkh);
    cudaGetSymbolAddress((void**)&wvh, g_wvh);
    cudaGetSymbolAddress((void**)&woh, g_woh);
    cudaGetSymbolAddress((void**)&q, g_q);
    cudaGetSymbolAddress((void**)&k, g_k);
    cudaGetSymbolAddress((void**)&v, g_v);
    cudaGetSymbolAddress((void**)&a, g_a);

    // 1/sqrt(128) * log2(e): softmax in base-2 domain
    const float scale = 0.08838834764831845f * 1.4426950408889634f;

    conv_all<<<dim3(512, 5), 256>>>(x, Wq, Wk, Wv, Wo,
                                    xh, wqh, wkh, wvh, woh, scale);

    const int gemm_smem = 3 * GSTG * 2;  // 56832
    cudaFuncSetAttribute(gemm_f16<true>,
                         cudaFuncAttributeMaxDynamicSharedMemorySize, gemm_smem);
    cudaFuncSetAttribute(gemm_f16<false>,
                         cudaFuncAttributeMaxDynamicSharedMemorySize, gemm_smem);
    const int attn_smem = (128 * QP + 4 * KVSZ) * 2;  // 104448
    cudaFuncSetAttribute(attn_f16,
                         cudaFuncAttributeMaxDynamicSharedMemorySize, attn_smem);

    // fused QKV projection (half out)
    gemm_f16<true><<<dim3(DD / 128, MTOT / 128, 3), 128, gemm_smem>>>(
        xh, wqh, wkh, wvh, q, k, v, MTOT, DD, DD);

    attn_f16<<<dim3(NN / 128, BB * 8), 128, attn_smem>>>(q, k, v, a);

    // output projection (float out)
    gemm_f16<false><<<dim3(DD / 128, MTOT / 128, 1), 128, gemm_smem>>>(
        a, woh, woh, woh, out, out, out, MTOT, DD, DD);
}